// round 1
// baseline (speedup 1.0000x reference)
#include <cuda_runtime.h>
#include <math.h>

#define D_MODEL 1024
#define D_FF    4096
#define SEQ     2048
#define BATCH   2
#define NTOK    (BATCH*SEQ)   // 4096
#define NHEAD   16
#define HDIM    64

// ---------------- scratch (device globals; no allocation allowed) ----------
__device__ float g_q  [NTOK * D_MODEL];
__device__ float g_k  [NTOK * D_MODEL];
__device__ float g_v  [NTOK * D_MODEL];
__device__ float g_ctx[NTOK * D_MODEL];
__device__ float g_t1 [NTOK * D_MODEL];
__device__ float g_h  [NTOK * D_MODEL];
__device__ float g_ff [NTOK * D_FF];

// ---------------------------------------------------------------------------
// Tiled SGEMM: C[N,M] = A[N,K] @ W[K,M] + bias (+ optional ReLU)
// 128x128 tile, K-step 8, 256 threads, 8x8 microtile per thread.
// All of N,M multiples of 128 and K multiple of 8 (true for every call here).
// ---------------------------------------------------------------------------
template <bool RELU>
__global__ void __launch_bounds__(256, 2) gemm_bias_kernel(
    const float* __restrict__ A, const float* __restrict__ W,
    const float* __restrict__ bias, float* __restrict__ C,
    int N, int K, int M)
{
    __shared__ float As[8 * 128];   // transposed: As[k][m]
    __shared__ float Bs[8 * 128];   // Bs[k][n]

    const int tid = threadIdx.x;
    const int tx  = tid & 15;       // 0..15 -> 8 cols each
    const int ty  = tid >> 4;       // 0..15 -> 8 rows each
    const int row0 = blockIdx.y * 128;
    const int col0 = blockIdx.x * 128;

    // loader mapping
    const int arow = tid >> 1;            // 0..127
    const int acol = (tid & 1) << 2;      // 0 or 4
    const int brow = tid >> 5;            // 0..7
    const int bcol = (tid & 31) << 2;     // 0..124

    const float* Ap = A + (size_t)(row0 + arow) * K + acol;
    const float* Bp = W + (size_t)brow * M + col0 + bcol;

    float acc[8][8];
#pragma unroll
    for (int i = 0; i < 8; i++)
#pragma unroll
        for (int j = 0; j < 8; j++) acc[i][j] = 0.0f;

    for (int k0 = 0; k0 < K; k0 += 8) {
        float4 av = *(const float4*)Ap;
        float4 bv = *(const float4*)Bp;
        As[(acol + 0) * 128 + arow] = av.x;
        As[(acol + 1) * 128 + arow] = av.y;
        As[(acol + 2) * 128 + arow] = av.z;
        As[(acol + 3) * 128 + arow] = av.w;
        *(float4*)(&Bs[brow * 128 + bcol]) = bv;
        __syncthreads();

#pragma unroll
        for (int kk = 0; kk < 8; kk++) {
            float ra[8], rb[8];
            *(float4*)(ra)     = *(const float4*)(&As[kk * 128 + ty * 8]);
            *(float4*)(ra + 4) = *(const float4*)(&As[kk * 128 + ty * 8 + 4]);
            *(float4*)(rb)     = *(const float4*)(&Bs[kk * 128 + tx * 8]);
            *(float4*)(rb + 4) = *(const float4*)(&Bs[kk * 128 + tx * 8 + 4]);
#pragma unroll
            for (int i = 0; i < 8; i++)
#pragma unroll
                for (int j = 0; j < 8; j++)
                    acc[i][j] = fmaf(ra[i], rb[j], acc[i][j]);
        }
        __syncthreads();
        Ap += 8;
        Bp += (size_t)8 * M;
    }

    float bj[8];
#pragma unroll
    for (int j = 0; j < 8; j++) bj[j] = bias[col0 + tx * 8 + j];

#pragma unroll
    for (int i = 0; i < 8; i++) {
        float* Cp = C + (size_t)(row0 + ty * 8 + i) * M + col0 + tx * 8;
        float4 o0, o1;
        float v;
        v = acc[i][0] + bj[0]; if (RELU) v = fmaxf(v, 0.0f); o0.x = v;
        v = acc[i][1] + bj[1]; if (RELU) v = fmaxf(v, 0.0f); o0.y = v;
        v = acc[i][2] + bj[2]; if (RELU) v = fmaxf(v, 0.0f); o0.z = v;
        v = acc[i][3] + bj[3]; if (RELU) v = fmaxf(v, 0.0f); o0.w = v;
        v = acc[i][4] + bj[4]; if (RELU) v = fmaxf(v, 0.0f); o1.x = v;
        v = acc[i][5] + bj[5]; if (RELU) v = fmaxf(v, 0.0f); o1.y = v;
        v = acc[i][6] + bj[6]; if (RELU) v = fmaxf(v, 0.0f); o1.z = v;
        v = acc[i][7] + bj[7]; if (RELU) v = fmaxf(v, 0.0f); o1.w = v;
        *(float4*)(Cp)     = o0;
        *(float4*)(Cp + 4) = o1;
    }
}

// ---------------------------------------------------------------------------
// Fused attention: per CTA = one (b, h, 64-row q block). Online softmax.
// Q/K/V layout: [token, D_MODEL], channel = h*64 + d.
// smem: Qs[d][i] 64x64, Ks[d][j] 64x64, Vs[j][n] 64x64, Ps[j][i] pitch 65.
// ---------------------------------------------------------------------------
#define ATT_SMEM_FLOATS (3 * 4096 + 64 * 65)

__global__ void __launch_bounds__(256) attention_kernel(
    const float* __restrict__ Q, const float* __restrict__ K,
    const float* __restrict__ V, float* __restrict__ O)
{
    extern __shared__ float sm[];
    float* Qs = sm;            // [d*64 + i]
    float* Ks = sm + 4096;     // [d*64 + j]
    float* Vs = sm + 8192;     // [j*64 + n]
    float* Ps = sm + 12288;    // [j*65 + i]

    const int tid = threadIdx.x;
    const int tx  = tid & 15;
    const int ty  = tid >> 4;
    const int bh  = blockIdx.y;
    const int b   = bh >> 4;
    const int h   = bh & 15;
    const int q0  = blockIdx.x * 64;

    const float* Qb = Q + ((size_t)(b * SEQ + q0)) * D_MODEL + h * HDIM;
    const float* Kb = K + ((size_t)(b * SEQ)) * D_MODEL + h * HDIM;
    const float* Vb = V + ((size_t)(b * SEQ)) * D_MODEL + h * HDIM;

    // load Q tile transposed, pre-scaled by 1/sqrt(64)
    for (int t = tid; t < 64 * 16; t += 256) {
        int r  = t >> 4;
        int c4 = (t & 15) << 2;
        float4 v = *(const float4*)(Qb + (size_t)r * D_MODEL + c4);
        Qs[(c4 + 0) * 64 + r] = v.x * 0.125f;
        Qs[(c4 + 1) * 64 + r] = v.y * 0.125f;
        Qs[(c4 + 2) * 64 + r] = v.z * 0.125f;
        Qs[(c4 + 3) * 64 + r] = v.w * 0.125f;
    }

    const int i0 = ty * 4;
    const int j0 = tx * 4;

    float m[4], l[4], o[4][4];
#pragma unroll
    for (int i = 0; i < 4; i++) {
        m[i] = -1e30f;
        l[i] = 0.0f;
#pragma unroll
        for (int n = 0; n < 4; n++) o[i][n] = 0.0f;
    }

    for (int kt = 0; kt < SEQ / 64; kt++) {
        __syncthreads();  // protect Ks/Vs against previous iteration readers
        const float* Kt = Kb + (size_t)kt * 64 * D_MODEL;
        const float* Vt = Vb + (size_t)kt * 64 * D_MODEL;
        for (int t = tid; t < 64 * 16; t += 256) {
            int r  = t >> 4;
            int c4 = (t & 15) << 2;
            float4 kv = *(const float4*)(Kt + (size_t)r * D_MODEL + c4);
            Ks[(c4 + 0) * 64 + r] = kv.x;
            Ks[(c4 + 1) * 64 + r] = kv.y;
            Ks[(c4 + 2) * 64 + r] = kv.z;
            Ks[(c4 + 3) * 64 + r] = kv.w;
            float4 vv = *(const float4*)(Vt + (size_t)r * D_MODEL + c4);
            *(float4*)(&Vs[r * 64 + c4]) = vv;
        }
        __syncthreads();

        // S = Q @ K^T (tile 64x64), each thread 4x4
        float s[4][4];
#pragma unroll
        for (int i = 0; i < 4; i++)
#pragma unroll
            for (int j = 0; j < 4; j++) s[i][j] = 0.0f;

#pragma unroll 4
        for (int d = 0; d < 64; d++) {
            float qa[4], ka[4];
            *(float4*)qa = *(const float4*)(&Qs[d * 64 + i0]);
            *(float4*)ka = *(const float4*)(&Ks[d * 64 + j0]);
#pragma unroll
            for (int i = 0; i < 4; i++)
#pragma unroll
                for (int j = 0; j < 4; j++)
                    s[i][j] = fmaf(qa[i], ka[j], s[i][j]);
        }

        // online softmax per row (row group = 16 lanes sharing ty)
#pragma unroll
        for (int ii = 0; ii < 4; ii++) {
            float tm = fmaxf(fmaxf(s[ii][0], s[ii][1]), fmaxf(s[ii][2], s[ii][3]));
#pragma unroll
            for (int w = 8; w >= 1; w >>= 1)
                tm = fmaxf(tm, __shfl_xor_sync(0xffffffffu, tm, w));
            float mn = fmaxf(m[ii], tm);
            float c  = __expf(m[ii] - mn);
            m[ii] = mn;
            float p[4];
            float rs = 0.0f;
#pragma unroll
            for (int jj = 0; jj < 4; jj++) {
                p[jj] = __expf(s[ii][jj] - mn);
                rs += p[jj];
            }
#pragma unroll
            for (int w = 8; w >= 1; w >>= 1)
                rs += __shfl_xor_sync(0xffffffffu, rs, w);
            l[ii] = l[ii] * c + rs;
#pragma unroll
            for (int nn = 0; nn < 4; nn++) o[ii][nn] *= c;
#pragma unroll
            for (int jj = 0; jj < 4; jj++)
                Ps[(j0 + jj) * 65 + i0 + ii] = p[jj];
        }
        __syncthreads();

        // O += P @ V
#pragma unroll 4
        for (int j = 0; j < 64; j++) {
            float pa[4], va[4];
            pa[0] = Ps[j * 65 + i0 + 0];
            pa[1] = Ps[j * 65 + i0 + 1];
            pa[2] = Ps[j * 65 + i0 + 2];
            pa[3] = Ps[j * 65 + i0 + 3];
            *(float4*)va = *(const float4*)(&Vs[j * 64 + j0]);
#pragma unroll
            for (int i = 0; i < 4; i++)
#pragma unroll
                for (int n = 0; n < 4; n++)
                    o[i][n] = fmaf(pa[i], va[n], o[i][n]);
        }
    }

    // normalize and write ctx
#pragma unroll
    for (int ii = 0; ii < 4; ii++) {
        float inv = 1.0f / l[ii];
        float4 ov;
        ov.x = o[ii][0] * inv;
        ov.y = o[ii][1] * inv;
        ov.z = o[ii][2] * inv;
        ov.w = o[ii][3] * inv;
        size_t tok = (size_t)(b * SEQ + q0 + i0 + ii);
        *(float4*)(O + tok * D_MODEL + h * HDIM + j0) = ov;
    }
}

// ---------------------------------------------------------------------------
// Fused residual add + LayerNorm: out = LN(a + r) * g + beta. One CTA per row.
// ---------------------------------------------------------------------------
__global__ void __launch_bounds__(256) add_ln_kernel(
    const float* __restrict__ A, const float* __restrict__ R,
    const float* __restrict__ g, const float* __restrict__ beta,
    float* __restrict__ out)
{
    const int row = blockIdx.x;
    const int t   = threadIdx.x;

    float4 a = *(const float4*)(A + (size_t)row * D_MODEL + t * 4);
    float4 r = *(const float4*)(R + (size_t)row * D_MODEL + t * 4);
    float x0 = a.x + r.x, x1 = a.y + r.y, x2 = a.z + r.z, x3 = a.w + r.w;

    float sum = x0 + x1 + x2 + x3;
    float sq  = x0 * x0 + x1 * x1 + x2 * x2 + x3 * x3;

#pragma unroll
    for (int w = 16; w >= 1; w >>= 1) {
        sum += __shfl_xor_sync(0xffffffffu, sum, w);
        sq  += __shfl_xor_sync(0xffffffffu, sq, w);
    }
    __shared__ float ssum[8], ssq[8];
    __shared__ float s_mu, s_rstd;
    if ((t & 31) == 0) {
        ssum[t >> 5] = sum;
        ssq[t >> 5]  = sq;
    }
    __syncthreads();
    if (t == 0) {
        float S = 0.0f, Q = 0.0f;
#pragma unroll
        for (int i = 0; i < 8; i++) { S += ssum[i]; Q += ssq[i]; }
        float mu  = S * (1.0f / D_MODEL);
        float var = Q * (1.0f / D_MODEL) - mu * mu;
        s_mu   = mu;
        s_rstd = rsqrtf(var + 1e-5f);
    }
    __syncthreads();
    float mu = s_mu, rstd = s_rstd;

    float4 gg = *(const float4*)(g + t * 4);
    float4 bb = *(const float4*)(beta + t * 4);
    float4 ov;
    ov.x = (x0 - mu) * rstd * gg.x + bb.x;
    ov.y = (x1 - mu) * rstd * gg.y + bb.y;
    ov.z = (x2 - mu) * rstd * gg.z + bb.z;
    ov.w = (x3 - mu) * rstd * gg.w + bb.w;
    *(float4*)(out + (size_t)row * D_MODEL + t * 4) = ov;
}

// ---------------------------------------------------------------------------
extern "C" void kernel_launch(void* const* d_in, const int* in_sizes, int n_in,
                              void* d_out, int out_size)
{
    (void)in_sizes; (void)n_in; (void)out_size;

    const float* x     = (const float*)d_in[0];
    const float* w_q   = (const float*)d_in[1];
    const float* b_q   = (const float*)d_in[2];
    const float* w_k   = (const float*)d_in[3];
    const float* b_k   = (const float*)d_in[4];
    const float* w_v   = (const float*)d_in[5];
    const float* b_v   = (const float*)d_in[6];
    const float* w_o   = (const float*)d_in[7];
    const float* b_o   = (const float*)d_in[8];
    const float* w_ff1 = (const float*)d_in[9];
    const float* b_ff1 = (const float*)d_in[10];
    const float* w_ff2 = (const float*)d_in[11];
    const float* b_ff2 = (const float*)d_in[12];
    const float* ln1_g = (const float*)d_in[13];
    const float* ln1_b = (const float*)d_in[14];
    const float* ln2_g = (const float*)d_in[15];
    const float* ln2_b = (const float*)d_in[16];
    float* out = (float*)d_out;

    float *q, *k, *v, *ctx, *t1, *h, *ff;
    cudaGetSymbolAddress((void**)&q,   g_q);
    cudaGetSymbolAddress((void**)&k,   g_k);
    cudaGetSymbolAddress((void**)&v,   g_v);
    cudaGetSymbolAddress((void**)&ctx, g_ctx);
    cudaGetSymbolAddress((void**)&t1,  g_t1);
    cudaGetSymbolAddress((void**)&h,   g_h);
    cudaGetSymbolAddress((void**)&ff,  g_ff);

    const int att_smem = ATT_SMEM_FLOATS * (int)sizeof(float);
    cudaFuncSetAttribute(attention_kernel,
                         cudaFuncAttributeMaxDynamicSharedMemorySize, att_smem);

    dim3 blk(256);

    // QKV projections
    dim3 gQ(D_MODEL / 128, NTOK / 128);
    gemm_bias_kernel<false><<<gQ, blk>>>(x, w_q, b_q, q, NTOK, D_MODEL, D_MODEL);
    gemm_bias_kernel<false><<<gQ, blk>>>(x, w_k, b_k, k, NTOK, D_MODEL, D_MODEL);
    gemm_bias_kernel<false><<<gQ, blk>>>(x, w_v, b_v, v, NTOK, D_MODEL, D_MODEL);

    // fused attention -> ctx
    attention_kernel<<<dim3(SEQ / 64, BATCH * NHEAD), blk, att_smem>>>(q, k, v, ctx);

    // output projection
    gemm_bias_kernel<false><<<gQ, blk>>>(ctx, w_o, b_o, t1, NTOK, D_MODEL, D_MODEL);

    // AddNorm1
    add_ln_kernel<<<NTOK, 256>>>(x, t1, ln1_g, ln1_b, h);

    // FFN
    dim3 gF1(D_FF / 128, NTOK / 128);
    gemm_bias_kernel<true><<<gF1, blk>>>(h, w_ff1, b_ff1, ff, NTOK, D_MODEL, D_FF);
    gemm_bias_kernel<false><<<gQ, blk>>>(ff, w_ff2, b_ff2, t1, NTOK, D_FF, D_MODEL);

    // AddNorm2 -> output
    add_ln_kernel<<<NTOK, 256>>>(h, t1, ln2_g, ln2_b, out);
}

// round 2
// speedup vs baseline: 1.8796x; 1.8796x over previous
#include <cuda_runtime.h>
#include <math.h>
#include <stdint.h>

#define D_MODEL 1024
#define D_FF    4096
#define SEQ     2048
#define BATCH   2
#define NTOK    (BATCH*SEQ)   // 4096
#define NHEAD   16
#define HDIM    64

// ---------------- scratch (device globals; no allocation allowed) ----------
__device__ float g_q  [NTOK * D_MODEL];
__device__ float g_k  [NTOK * D_MODEL];
__device__ float g_v  [NTOK * D_MODEL];
__device__ float g_ctx[NTOK * D_MODEL];
__device__ float g_t1 [NTOK * D_MODEL];
__device__ float g_h  [NTOK * D_MODEL];
__device__ float g_ff [NTOK * D_FF];

// ===========================================================================
// TF32 tensor-core GEMM: C[N,M] = A[N,K] @ W[K,M] + bias (+ReLU)
// CTA tile 128x128, BK=32, 3-stage cp.async pipeline, 256 threads (8 warps,
// 2x4 warp grid, 64x32 warp tile), mma.sync.m16n8k8.tf32.
// As stored [m][k] (32 floats/row) with 16B-unit xor swizzle for ldmatrix.
// Bs stored [k][n] with +8 float row pad for conflict-free LDS.
// ===========================================================================
#define BK 32
#define AS_FLOATS (128 * 32)
#define BS_STRIDE 136
#define BS_FLOATS (32 * BS_STRIDE)
#define STAGE_FLOATS (AS_FLOATS + BS_FLOATS)
#define GEMM_SMEM_BYTES (3 * STAGE_FLOATS * (int)sizeof(float))

__device__ __forceinline__ void cp_async16(void* smem_dst, const void* gmem_src) {
    uint32_t da = (uint32_t)__cvta_generic_to_shared(smem_dst);
    asm volatile("cp.async.cg.shared.global [%0], [%1], 16;\n" :: "r"(da), "l"(gmem_src));
}
__device__ __forceinline__ void cp_commit() {
    asm volatile("cp.async.commit_group;\n");
}
__device__ __forceinline__ void cp_wait1() {
    asm volatile("cp.async.wait_group 1;\n");
}
__device__ __forceinline__ uint32_t f2tf32(float f) {
    uint32_t r;
    asm("cvt.rna.tf32.f32 %0, %1;" : "=r"(r) : "f"(f));
    return r;
}

__device__ __forceinline__ void gemm_tf32_body(
    float* sm,
    const float* __restrict__ A, const float* __restrict__ W,
    const float* __restrict__ bias, float* __restrict__ C,
    int K, int M, int row0, int col0, bool relu)
{
    const int tid  = threadIdx.x;
    const int lane = tid & 31;
    const int wid  = tid >> 5;
    const int warp_m = wid & 1;   // 0..1 -> 64 rows each
    const int warp_n = wid >> 1;  // 0..3 -> 32 cols each

    float acc[4][4][4];
#pragma unroll
    for (int mt = 0; mt < 4; mt++)
#pragma unroll
        for (int nt = 0; nt < 4; nt++)
#pragma unroll
            for (int r = 0; r < 4; r++) acc[mt][nt][r] = 0.0f;

    const int KT = K / BK;

    // ---- stage loader ----
    auto load_stage = [&](int kt, int stage) {
        float* As = sm + stage * STAGE_FLOATS;
        float* Bs = As + AS_FLOATS;
        const int k0 = kt * BK;
#pragma unroll
        for (int i = 0; i < 4; i++) {
            int c = tid + 256 * i;            // 0..1023
            int r = c >> 3, u = c & 7;        // A: row 0..127, 16B unit 0..7
            const float* src = A + (size_t)(row0 + r) * K + k0 + u * 4;
            float* dst = As + r * 32 + ((u ^ (r & 7)) << 2);
            cp_async16(dst, src);
        }
#pragma unroll
        for (int i = 0; i < 4; i++) {
            int c = tid + 256 * i;
            int r = c >> 5, u = c & 31;       // B: krow 0..31, unit 0..31
            const float* src = W + (size_t)(k0 + r) * M + col0 + u * 4;
            float* dst = Bs + r * BS_STRIDE + u * 4;
            cp_async16(dst, src);
        }
        cp_commit();
    };

    load_stage(0, 0);
    load_stage(1, 1);

    for (int kt = 0; kt < KT; kt++) {
        cp_wait1();
        __syncthreads();
        if (kt + 2 < KT) load_stage(kt + 2, (kt + 2) % 3);
        else cp_commit();  // keep group accounting uniform

        float* As = sm + (kt % 3) * STAGE_FLOATS;
        float* Bs = As + AS_FLOATS;

#pragma unroll
        for (int k8 = 0; k8 < 4; k8++) {
            // A fragments via ldmatrix.x4 (one per 16-row m-tile)
            uint32_t a[4][4];
#pragma unroll
            for (int mt = 0; mt < 4; mt++) {
                int mat  = lane >> 3;                       // 0..3
                int mrow = warp_m * 64 + mt * 16 + (lane & 7) + (mat & 1) * 8;
                int u    = k8 * 2 + (mat >> 1);             // 16B unit within row
                uint32_t addr = (uint32_t)__cvta_generic_to_shared(
                    As + mrow * 32 + ((u ^ (mrow & 7)) << 2));
                asm volatile(
                    "ldmatrix.sync.aligned.m8n8.x4.shared.b16 {%0,%1,%2,%3}, [%4];"
                    : "=r"(a[mt][0]), "=r"(a[mt][1]), "=r"(a[mt][2]), "=r"(a[mt][3])
                    : "r"(addr));
#pragma unroll
                for (int r = 0; r < 4; r++)
                    a[mt][r] = f2tf32(__uint_as_float(a[mt][r]));
            }
            // B fragments via LDS (conflict-free with +8 pad)
            uint32_t b[4][2];
#pragma unroll
            for (int nt = 0; nt < 4; nt++) {
                int n = warp_n * 32 + nt * 8 + (lane >> 2);
                float b0 = Bs[(k8 * 8 + (lane & 3)) * BS_STRIDE + n];
                float b1 = Bs[(k8 * 8 + 4 + (lane & 3)) * BS_STRIDE + n];
                b[nt][0] = f2tf32(b0);
                b[nt][1] = f2tf32(b1);
            }
#pragma unroll
            for (int mt = 0; mt < 4; mt++)
#pragma unroll
                for (int nt = 0; nt < 4; nt++) {
                    asm volatile(
                        "mma.sync.aligned.m16n8k8.row.col.f32.tf32.tf32.f32 "
                        "{%0,%1,%2,%3}, {%4,%5,%6,%7}, {%8,%9}, {%0,%1,%2,%3};"
                        : "+f"(acc[mt][nt][0]), "+f"(acc[mt][nt][1]),
                          "+f"(acc[mt][nt][2]), "+f"(acc[mt][nt][3])
                        : "r"(a[mt][0]), "r"(a[mt][1]), "r"(a[mt][2]), "r"(a[mt][3]),
                          "r"(b[nt][0]), "r"(b[nt][1]));
                }
        }
        __syncthreads();
    }

    // ---- epilogue: bias (+ReLU), float2 stores ----
#pragma unroll
    for (int nt = 0; nt < 4; nt++) {
        int ncol = col0 + warp_n * 32 + nt * 8 + (lane & 3) * 2;
        float bj0 = bias[ncol];
        float bj1 = bias[ncol + 1];
#pragma unroll
        for (int mt = 0; mt < 4; mt++) {
            int r0 = row0 + warp_m * 64 + mt * 16 + (lane >> 2);
            float v0 = acc[mt][nt][0] + bj0;
            float v1 = acc[mt][nt][1] + bj1;
            float v2 = acc[mt][nt][2] + bj0;
            float v3 = acc[mt][nt][3] + bj1;
            if (relu) {
                v0 = fmaxf(v0, 0.0f); v1 = fmaxf(v1, 0.0f);
                v2 = fmaxf(v2, 0.0f); v3 = fmaxf(v3, 0.0f);
            }
            *(float2*)(C + (size_t)r0 * M + ncol)       = make_float2(v0, v1);
            *(float2*)(C + (size_t)(r0 + 8) * M + ncol) = make_float2(v2, v3);
        }
    }
}

template <bool RELU>
__global__ void __launch_bounds__(256) gemm_tf32_kernel(
    const float* __restrict__ A, const float* __restrict__ W,
    const float* __restrict__ bias, float* __restrict__ C, int K, int M)
{
    extern __shared__ float sm[];
    gemm_tf32_body(sm, A, W, bias, C, K, M,
                   blockIdx.y * 128, blockIdx.x * 128, RELU);
}

// QKV fused in one launch via blockIdx.z
__global__ void __launch_bounds__(256) qkv_tf32_kernel(
    const float* __restrict__ x,
    const float* __restrict__ wq, const float* __restrict__ bq,
    const float* __restrict__ wk, const float* __restrict__ bk,
    const float* __restrict__ wv, const float* __restrict__ bv,
    float* __restrict__ q, float* __restrict__ k, float* __restrict__ v,
    int K, int M)
{
    extern __shared__ float sm[];
    const int z = blockIdx.z;
    const float* W    = (z == 0) ? wq : (z == 1) ? wk : wv;
    const float* bias = (z == 0) ? bq : (z == 1) ? bk : bv;
    float*       C    = (z == 0) ? q  : (z == 1) ? k  : v;
    gemm_tf32_body(sm, x, W, bias, C, K, M,
                   blockIdx.y * 128, blockIdx.x * 128, false);
}

// ---------------------------------------------------------------------------
// Fused attention (fp32, unchanged from R1): per CTA = (b, h, 64 q rows).
// ---------------------------------------------------------------------------
#define ATT_SMEM_FLOATS (3 * 4096 + 64 * 65)

__global__ void __launch_bounds__(256) attention_kernel(
    const float* __restrict__ Q, const float* __restrict__ K,
    const float* __restrict__ V, float* __restrict__ O)
{
    extern __shared__ float sm[];
    float* Qs = sm;            // [d*64 + i]
    float* Ks = sm + 4096;     // [d*64 + j]
    float* Vs = sm + 8192;     // [j*64 + n]
    float* Ps = sm + 12288;    // [j*65 + i]

    const int tid = threadIdx.x;
    const int tx  = tid & 15;
    const int ty  = tid >> 4;
    const int bh  = blockIdx.y;
    const int b   = bh >> 4;
    const int h   = bh & 15;
    const int q0  = blockIdx.x * 64;

    const float* Qb = Q + ((size_t)(b * SEQ + q0)) * D_MODEL + h * HDIM;
    const float* Kb = K + ((size_t)(b * SEQ)) * D_MODEL + h * HDIM;
    const float* Vb = V + ((size_t)(b * SEQ)) * D_MODEL + h * HDIM;

    for (int t = tid; t < 64 * 16; t += 256) {
        int r  = t >> 4;
        int c4 = (t & 15) << 2;
        float4 v = *(const float4*)(Qb + (size_t)r * D_MODEL + c4);
        Qs[(c4 + 0) * 64 + r] = v.x * 0.125f;
        Qs[(c4 + 1) * 64 + r] = v.y * 0.125f;
        Qs[(c4 + 2) * 64 + r] = v.z * 0.125f;
        Qs[(c4 + 3) * 64 + r] = v.w * 0.125f;
    }

    const int i0 = ty * 4;
    const int j0 = tx * 4;

    float m[4], l[4], o[4][4];
#pragma unroll
    for (int i = 0; i < 4; i++) {
        m[i] = -1e30f;
        l[i] = 0.0f;
#pragma unroll
        for (int n = 0; n < 4; n++) o[i][n] = 0.0f;
    }

    for (int kt = 0; kt < SEQ / 64; kt++) {
        __syncthreads();
        const float* Kt = Kb + (size_t)kt * 64 * D_MODEL;
        const float* Vt = Vb + (size_t)kt * 64 * D_MODEL;
        for (int t = tid; t < 64 * 16; t += 256) {
            int r  = t >> 4;
            int c4 = (t & 15) << 2;
            float4 kv = *(const float4*)(Kt + (size_t)r * D_MODEL + c4);
            Ks[(c4 + 0) * 64 + r] = kv.x;
            Ks[(c4 + 1) * 64 + r] = kv.y;
            Ks[(c4 + 2) * 64 + r] = kv.z;
            Ks[(c4 + 3) * 64 + r] = kv.w;
            float4 vv = *(const float4*)(Vt + (size_t)r * D_MODEL + c4);
            *(float4*)(&Vs[r * 64 + c4]) = vv;
        }
        __syncthreads();

        float s[4][4];
#pragma unroll
        for (int i = 0; i < 4; i++)
#pragma unroll
            for (int j = 0; j < 4; j++) s[i][j] = 0.0f;

#pragma unroll 4
        for (int d = 0; d < 64; d++) {
            float qa[4], ka[4];
            *(float4*)qa = *(const float4*)(&Qs[d * 64 + i0]);
            *(float4*)ka = *(const float4*)(&Ks[d * 64 + j0]);
#pragma unroll
            for (int i = 0; i < 4; i++)
#pragma unroll
                for (int j = 0; j < 4; j++)
                    s[i][j] = fmaf(qa[i], ka[j], s[i][j]);
        }

#pragma unroll
        for (int ii = 0; ii < 4; ii++) {
            float tm = fmaxf(fmaxf(s[ii][0], s[ii][1]), fmaxf(s[ii][2], s[ii][3]));
#pragma unroll
            for (int w = 8; w >= 1; w >>= 1)
                tm = fmaxf(tm, __shfl_xor_sync(0xffffffffu, tm, w));
            float mn = fmaxf(m[ii], tm);
            float c  = __expf(m[ii] - mn);
            m[ii] = mn;
            float p[4];
            float rs = 0.0f;
#pragma unroll
            for (int jj = 0; jj < 4; jj++) {
                p[jj] = __expf(s[ii][jj] - mn);
                rs += p[jj];
            }
#pragma unroll
            for (int w = 8; w >= 1; w >>= 1)
                rs += __shfl_xor_sync(0xffffffffu, rs, w);
            l[ii] = l[ii] * c + rs;
#pragma unroll
            for (int nn = 0; nn < 4; nn++) o[ii][nn] *= c;
#pragma unroll
            for (int jj = 0; jj < 4; jj++)
                Ps[(j0 + jj) * 65 + i0 + ii] = p[jj];
        }
        __syncthreads();

#pragma unroll 4
        for (int j = 0; j < 64; j++) {
            float pa[4], va[4];
            pa[0] = Ps[j * 65 + i0 + 0];
            pa[1] = Ps[j * 65 + i0 + 1];
            pa[2] = Ps[j * 65 + i0 + 2];
            pa[3] = Ps[j * 65 + i0 + 3];
            *(float4*)va = *(const float4*)(&Vs[j * 64 + j0]);
#pragma unroll
            for (int i = 0; i < 4; i++)
#pragma unroll
                for (int n = 0; n < 4; n++)
                    o[i][n] = fmaf(pa[i], va[n], o[i][n]);
        }
    }

#pragma unroll
    for (int ii = 0; ii < 4; ii++) {
        float inv = 1.0f / l[ii];
        float4 ov;
        ov.x = o[ii][0] * inv;
        ov.y = o[ii][1] * inv;
        ov.z = o[ii][2] * inv;
        ov.w = o[ii][3] * inv;
        size_t tok = (size_t)(b * SEQ + q0 + i0 + ii);
        *(float4*)(O + tok * D_MODEL + h * HDIM + j0) = ov;
    }
}

// ---------------------------------------------------------------------------
// Fused residual add + LayerNorm (unchanged)
// ---------------------------------------------------------------------------
__global__ void __launch_bounds__(256) add_ln_kernel(
    const float* __restrict__ A, const float* __restrict__ R,
    const float* __restrict__ g, const float* __restrict__ beta,
    float* __restrict__ out)
{
    const int row = blockIdx.x;
    const int t   = threadIdx.x;

    float4 a = *(const float4*)(A + (size_t)row * D_MODEL + t * 4);
    float4 r = *(const float4*)(R + (size_t)row * D_MODEL + t * 4);
    float x0 = a.x + r.x, x1 = a.y + r.y, x2 = a.z + r.z, x3 = a.w + r.w;

    float sum = x0 + x1 + x2 + x3;
    float sq  = x0 * x0 + x1 * x1 + x2 * x2 + x3 * x3;

#pragma unroll
    for (int w = 16; w >= 1; w >>= 1) {
        sum += __shfl_xor_sync(0xffffffffu, sum, w);
        sq  += __shfl_xor_sync(0xffffffffu, sq, w);
    }
    __shared__ float ssum[8], ssq[8];
    __shared__ float s_mu, s_rstd;
    if ((t & 31) == 0) {
        ssum[t >> 5] = sum;
        ssq[t >> 5]  = sq;
    }
    __syncthreads();
    if (t == 0) {
        float S = 0.0f, Q = 0.0f;
#pragma unroll
        for (int i = 0; i < 8; i++) { S += ssum[i]; Q += ssq[i]; }
        float mu  = S * (1.0f / D_MODEL);
        float var = Q * (1.0f / D_MODEL) - mu * mu;
        s_mu   = mu;
        s_rstd = rsqrtf(var + 1e-5f);
    }
    __syncthreads();
    float mu = s_mu, rstd = s_rstd;

    float4 gg = *(const float4*)(g + t * 4);
    float4 bb = *(const float4*)(beta + t * 4);
    float4 ov;
    ov.x = (x0 - mu) * rstd * gg.x + bb.x;
    ov.y = (x1 - mu) * rstd * gg.y + bb.y;
    ov.z = (x2 - mu) * rstd * gg.z + bb.z;
    ov.w = (x3 - mu) * rstd * gg.w + bb.w;
    *(float4*)(out + (size_t)row * D_MODEL + t * 4) = ov;
}

// ---------------------------------------------------------------------------
extern "C" void kernel_launch(void* const* d_in, const int* in_sizes, int n_in,
                              void* d_out, int out_size)
{
    (void)in_sizes; (void)n_in; (void)out_size;

    const float* x     = (const float*)d_in[0];
    const float* w_q   = (const float*)d_in[1];
    const float* b_q   = (const float*)d_in[2];
    const float* w_k   = (const float*)d_in[3];
    const float* b_k   = (const float*)d_in[4];
    const float* w_v   = (const float*)d_in[5];
    const float* b_v   = (const float*)d_in[6];
    const float* w_o   = (const float*)d_in[7];
    const float* b_o   = (const float*)d_in[8];
    const float* w_ff1 = (const float*)d_in[9];
    const float* b_ff1 = (const float*)d_in[10];
    const float* w_ff2 = (const float*)d_in[11];
    const float* b_ff2 = (const float*)d_in[12];
    const float* ln1_g = (const float*)d_in[13];
    const float* ln1_b = (const float*)d_in[14];
    const float* ln2_g = (const float*)d_in[15];
    const float* ln2_b = (const float*)d_in[16];
    float* out = (float*)d_out;

    float *q, *k, *v, *ctx, *t1, *h, *ff;
    cudaGetSymbolAddress((void**)&q,   g_q);
    cudaGetSymbolAddress((void**)&k,   g_k);
    cudaGetSymbolAddress((void**)&v,   g_v);
    cudaGetSymbolAddress((void**)&ctx, g_ctx);
    cudaGetSymbolAddress((void**)&t1,  g_t1);
    cudaGetSymbolAddress((void**)&h,   g_h);
    cudaGetSymbolAddress((void**)&ff,  g_ff);

    const int att_smem = ATT_SMEM_FLOATS * (int)sizeof(float);
    cudaFuncSetAttribute(attention_kernel,
                         cudaFuncAttributeMaxDynamicSharedMemorySize, att_smem);
    cudaFuncSetAttribute(qkv_tf32_kernel,
                         cudaFuncAttributeMaxDynamicSharedMemorySize, GEMM_SMEM_BYTES);
    cudaFuncSetAttribute(gemm_tf32_kernel<false>,
                         cudaFuncAttributeMaxDynamicSharedMemorySize, GEMM_SMEM_BYTES);
    cudaFuncSetAttribute(gemm_tf32_kernel<true>,
                         cudaFuncAttributeMaxDynamicSharedMemorySize, GEMM_SMEM_BYTES);

    dim3 blk(256);

    // QKV projections (fused launch, grid.z = 3)
    qkv_tf32_kernel<<<dim3(D_MODEL / 128, NTOK / 128, 3), blk, GEMM_SMEM_BYTES>>>(
        x, w_q, b_q, w_k, b_k, w_v, b_v, q, k, v, D_MODEL, D_MODEL);

    // fused attention -> ctx
    attention_kernel<<<dim3(SEQ / 64, BATCH * NHEAD), blk, att_smem>>>(q, k, v, ctx);

    // output projection
    gemm_tf32_kernel<false><<<dim3(D_MODEL / 128, NTOK / 128), blk, GEMM_SMEM_BYTES>>>(
        ctx, w_o, b_o, t1, D_MODEL, D_MODEL);

    // AddNorm1
    add_ln_kernel<<<NTOK, 256>>>(x, t1, ln1_g, ln1_b, h);

    // FFN
    gemm_tf32_kernel<true><<<dim3(D_FF / 128, NTOK / 128), blk, GEMM_SMEM_BYTES>>>(
        h, w_ff1, b_ff1, ff, D_MODEL, D_FF);
    gemm_tf32_kernel<false><<<dim3(D_MODEL / 128, NTOK / 128), blk, GEMM_SMEM_BYTES>>>(
        ff, w_ff2, b_ff2, t1, D_FF, D_MODEL);

    // AddNorm2 -> output
    add_ln_kernel<<<NTOK, 256>>>(h, t1, ln2_g, ln2_b, out);
}

// round 3
// speedup vs baseline: 3.6374x; 1.9352x over previous
#include <cuda_runtime.h>
#include <math.h>
#include <stdint.h>

#define D_MODEL 1024
#define D_FF    4096
#define SEQ     2048
#define BATCH   2
#define NTOK    (BATCH*SEQ)   // 4096
#define NHEAD   16
#define HDIM    64

// ---------------- scratch (device globals; no allocation allowed) ----------
__device__ float g_q  [NTOK * D_MODEL];
__device__ float g_k  [NTOK * D_MODEL];
__device__ float g_v  [NTOK * D_MODEL];
__device__ float g_ctx[NTOK * D_MODEL];
__device__ float g_t1 [NTOK * D_MODEL];
__device__ float g_h  [NTOK * D_MODEL];
__device__ float g_ht [NTOK * D_MODEL];
__device__ float g_ff [NTOK * D_FF];
// tf32-rounded copies of inputs/weights
__device__ float g_xt  [NTOK * D_MODEL];
__device__ float g_wqt [D_MODEL * D_MODEL];
__device__ float g_wkt [D_MODEL * D_MODEL];
__device__ float g_wvt [D_MODEL * D_MODEL];
__device__ float g_wot [D_MODEL * D_MODEL];
__device__ float g_ff1t[D_MODEL * D_FF];
__device__ float g_ff2t[D_FF * D_MODEL];

// ---------------------------------------------------------------------------
__device__ __forceinline__ void cp_async16(void* smem_dst, const void* gmem_src) {
    uint32_t da = (uint32_t)__cvta_generic_to_shared(smem_dst);
    asm volatile("cp.async.cg.shared.global [%0], [%1], 16;\n" :: "r"(da), "l"(gmem_src));
}
__device__ __forceinline__ void cp_commit() {
    asm volatile("cp.async.commit_group;\n");
}
__device__ __forceinline__ void cp_wait1() {
    asm volatile("cp.async.wait_group 1;\n");
}
__device__ __forceinline__ uint32_t f2tf32(float f) {
    uint32_t r;
    asm("cvt.rna.tf32.f32 %0, %1;" : "=r"(r) : "f"(f));
    return r;
}
__device__ __forceinline__ void mma_tf32(float* c, const uint32_t* a,
                                         uint32_t b0, uint32_t b1) {
    asm volatile(
        "mma.sync.aligned.m16n8k8.row.col.f32.tf32.tf32.f32 "
        "{%0,%1,%2,%3}, {%4,%5,%6,%7}, {%8,%9}, {%0,%1,%2,%3};"
        : "+f"(c[0]), "+f"(c[1]), "+f"(c[2]), "+f"(c[3])
        : "r"(a[0]), "r"(a[1]), "r"(a[2]), "r"(a[3]), "r"(b0), "r"(b1));
}
// fast exp2 on the FMA pipe (x <= 0), rel err ~2e-6
__device__ __forceinline__ float exp2p(float x) {
    x = fmaxf(x, -126.0f);
    float z = x + 12582912.0f;          // round-to-nearest in low mantissa
    float f = x - (z - 12582912.0f);    // f in [-0.5, 0.5]
    float p =            1.3333558146e-3f;
    p = fmaf(p, f, 9.6181291918e-3f);
    p = fmaf(p, f, 5.5504108664e-2f);
    p = fmaf(p, f, 2.4022650695e-1f);
    p = fmaf(p, f, 6.9314718056e-1f);
    p = fmaf(p, f, 1.0f);
    return __int_as_float((__float_as_int(z) << 23) + __float_as_int(p));
}

// ---------------------------------------------------------------------------
// prepass: round fp32 array to tf32 values (stored as fp32)
// ---------------------------------------------------------------------------
__global__ void round_tf32_kernel(const float4* __restrict__ src,
                                  float4* __restrict__ dst, int n4)
{
    int i = blockIdx.x * blockDim.x + threadIdx.x;
    if (i < n4) {
        float4 v = src[i];
        v.x = __uint_as_float(f2tf32(v.x));
        v.y = __uint_as_float(f2tf32(v.y));
        v.z = __uint_as_float(f2tf32(v.z));
        v.w = __uint_as_float(f2tf32(v.w));
        dst[i] = v;
    }
}

// ===========================================================================
// TF32 tensor-core GEMM (inputs pre-rounded to tf32; NO cvt in mainloop)
// C[N,M] = A[N,K] @ W[K,M] + bias (+ReLU) (+tf32-round of output)
// ===========================================================================
#define BK 32
#define AS_FLOATS (128 * 32)
#define BS_STRIDE 136
#define BS_FLOATS (32 * BS_STRIDE)
#define STAGE_FLOATS (AS_FLOATS + BS_FLOATS)
#define GEMM_SMEM_BYTES (3 * STAGE_FLOATS * (int)sizeof(float))

__device__ __forceinline__ void gemm_tf32_body(
    float* sm,
    const float* __restrict__ A, const float* __restrict__ W,
    const float* __restrict__ bias, float* __restrict__ C,
    int K, int M, int row0, int col0, bool relu, bool round_out)
{
    const int tid  = threadIdx.x;
    const int lane = tid & 31;
    const int wid  = tid >> 5;
    const int warp_m = wid & 1;
    const int warp_n = wid >> 1;

    float acc[4][4][4];
#pragma unroll
    for (int mt = 0; mt < 4; mt++)
#pragma unroll
        for (int nt = 0; nt < 4; nt++)
#pragma unroll
            for (int r = 0; r < 4; r++) acc[mt][nt][r] = 0.0f;

    const int KT = K / BK;

    auto load_stage = [&](int kt, int stage) {
        float* As = sm + stage * STAGE_FLOATS;
        float* Bs = As + AS_FLOATS;
        const int k0 = kt * BK;
#pragma unroll
        for (int i = 0; i < 4; i++) {
            int c = tid + 256 * i;
            int r = c >> 3, u = c & 7;
            const float* src = A + (size_t)(row0 + r) * K + k0 + u * 4;
            float* dst = As + r * 32 + ((u ^ (r & 7)) << 2);
            cp_async16(dst, src);
        }
#pragma unroll
        for (int i = 0; i < 4; i++) {
            int c = tid + 256 * i;
            int r = c >> 5, u = c & 31;
            const float* src = W + (size_t)(k0 + r) * M + col0 + u * 4;
            float* dst = Bs + r * BS_STRIDE + u * 4;
            cp_async16(dst, src);
        }
        cp_commit();
    };

    load_stage(0, 0);
    load_stage(1, 1);

    for (int kt = 0; kt < KT; kt++) {
        cp_wait1();
        __syncthreads();
        if (kt + 2 < KT) load_stage(kt + 2, (kt + 2) % 3);
        else cp_commit();

        float* As = sm + (kt % 3) * STAGE_FLOATS;
        float* Bs = As + AS_FLOATS;

#pragma unroll
        for (int k8 = 0; k8 < 4; k8++) {
            uint32_t a[4][4];
#pragma unroll
            for (int mt = 0; mt < 4; mt++) {
                int mat  = lane >> 3;
                int mrow = warp_m * 64 + mt * 16 + (lane & 7) + (mat & 1) * 8;
                int u    = k8 * 2 + (mat >> 1);
                uint32_t addr = (uint32_t)__cvta_generic_to_shared(
                    As + mrow * 32 + ((u ^ (mrow & 7)) << 2));
                asm volatile(
                    "ldmatrix.sync.aligned.m8n8.x4.shared.b16 {%0,%1,%2,%3}, [%4];"
                    : "=r"(a[mt][0]), "=r"(a[mt][1]), "=r"(a[mt][2]), "=r"(a[mt][3])
                    : "r"(addr));
            }
            uint32_t b[4][2];
#pragma unroll
            for (int nt = 0; nt < 4; nt++) {
                int n = warp_n * 32 + nt * 8 + (lane >> 2);
                b[nt][0] = __float_as_uint(Bs[(k8 * 8 + (lane & 3)) * BS_STRIDE + n]);
                b[nt][1] = __float_as_uint(Bs[(k8 * 8 + 4 + (lane & 3)) * BS_STRIDE + n]);
            }
#pragma unroll
            for (int mt = 0; mt < 4; mt++)
#pragma unroll
                for (int nt = 0; nt < 4; nt++)
                    mma_tf32(acc[mt][nt], a[mt], b[nt][0], b[nt][1]);
        }
        __syncthreads();
    }

#pragma unroll
    for (int nt = 0; nt < 4; nt++) {
        int ncol = col0 + warp_n * 32 + nt * 8 + (lane & 3) * 2;
        float bj0 = bias[ncol];
        float bj1 = bias[ncol + 1];
#pragma unroll
        for (int mt = 0; mt < 4; mt++) {
            int r0 = row0 + warp_m * 64 + mt * 16 + (lane >> 2);
            float v0 = acc[mt][nt][0] + bj0;
            float v1 = acc[mt][nt][1] + bj1;
            float v2 = acc[mt][nt][2] + bj0;
            float v3 = acc[mt][nt][3] + bj1;
            if (relu) {
                v0 = fmaxf(v0, 0.0f); v1 = fmaxf(v1, 0.0f);
                v2 = fmaxf(v2, 0.0f); v3 = fmaxf(v3, 0.0f);
            }
            if (round_out) {
                v0 = __uint_as_float(f2tf32(v0));
                v1 = __uint_as_float(f2tf32(v1));
                v2 = __uint_as_float(f2tf32(v2));
                v3 = __uint_as_float(f2tf32(v3));
            }
            *(float2*)(C + (size_t)r0 * M + ncol)       = make_float2(v0, v1);
            *(float2*)(C + (size_t)(r0 + 8) * M + ncol) = make_float2(v2, v3);
        }
    }
}

template <bool RELU, bool ROUND>
__global__ void __launch_bounds__(256) gemm_tf32_kernel(
    const float* __restrict__ A, const float* __restrict__ W,
    const float* __restrict__ bias, float* __restrict__ C, int K, int M)
{
    extern __shared__ float sm[];
    gemm_tf32_body(sm, A, W, bias, C, K, M,
                   blockIdx.y * 128, blockIdx.x * 128, RELU, ROUND);
}

__global__ void __launch_bounds__(256) qkv_tf32_kernel(
    const float* __restrict__ x,
    const float* __restrict__ wq, const float* __restrict__ bq,
    const float* __restrict__ wk, const float* __restrict__ bk,
    const float* __restrict__ wv, const float* __restrict__ bv,
    float* __restrict__ q, float* __restrict__ k, float* __restrict__ v,
    int K, int M)
{
    extern __shared__ float sm[];
    const int z = blockIdx.z;
    const float* W    = (z == 0) ? wq : (z == 1) ? wk : wv;
    const float* bias = (z == 0) ? bq : (z == 1) ? bk : bv;
    float*       C    = (z == 0) ? q  : (z == 1) ? k  : v;
    gemm_tf32_body(sm, x, W, bias, C, K, M,
                   blockIdx.y * 128, blockIdx.x * 128, false, true);
}

// ===========================================================================
// Flash attention, tf32 mma.sync, base-2 online softmax, poly exp2.
// CTA = (b,h) x 128 q rows; 8 warps x 16 q rows. K/V tiles 64x64 double-buffered.
// q,k,v are tf32-pre-rounded. Output ctx is tf32-rounded.
// ===========================================================================
#define KS_STRIDE 76
#define VS_STRIDE 72
#define KS_FLOATS (64 * KS_STRIDE)
#define VS_FLOATS (64 * VS_STRIDE)
#define P_FLOATS  (128 * 64)
#define ATT_SMEM_BYTES ((2 * KS_FLOATS + 2 * VS_FLOATS + P_FLOATS) * (int)sizeof(float))
#define QSCALE (0.125f * 1.4426950408889634f)   // 1/sqrt(64) * log2(e)

__global__ void __launch_bounds__(256, 1) attention_mma_kernel(
    const float* __restrict__ Q, const float* __restrict__ K,
    const float* __restrict__ V, float* __restrict__ O)
{
    extern __shared__ float sm[];
    float* Ks = sm;
    float* Vs = sm + 2 * KS_FLOATS;
    float* Ps = sm + 2 * KS_FLOATS + 2 * VS_FLOATS;

    const int tid  = threadIdx.x;
    const int lane = tid & 31;
    const int wid  = tid >> 5;
    const int b    = blockIdx.y >> 4;
    const int h    = blockIdx.y & 15;
    const int q0   = blockIdx.x * 128;
    const int qr   = q0 + wid * 16;

    const float* Qb = Q + ((size_t)(b * SEQ + qr)) * D_MODEL + h * HDIM;
    const float* Kb = K + ((size_t)(b * SEQ)) * D_MODEL + h * HDIM;
    const float* Vb = V + ((size_t)(b * SEQ)) * D_MODEL + h * HDIM;

    // Q fragments resident in registers (scaled, re-rounded)
    uint32_t qf[8][4];
    {
        const int r = lane >> 2, c = lane & 3;
#pragma unroll
        for (int k8 = 0; k8 < 8; k8++) {
            qf[k8][0] = f2tf32(Qb[(size_t)r * D_MODEL + k8 * 8 + c] * QSCALE);
            qf[k8][1] = f2tf32(Qb[(size_t)(r + 8) * D_MODEL + k8 * 8 + c] * QSCALE);
            qf[k8][2] = f2tf32(Qb[(size_t)r * D_MODEL + k8 * 8 + c + 4] * QSCALE);
            qf[k8][3] = f2tf32(Qb[(size_t)(r + 8) * D_MODEL + k8 * 8 + c + 4] * QSCALE);
        }
    }

    auto load_kv = [&](int kt, int st) {
        const float* Kt = Kb + (size_t)kt * 64 * D_MODEL;
        const float* Vt = Vb + (size_t)kt * 64 * D_MODEL;
        float* kd = Ks + st * KS_FLOATS;
        float* vd = Vs + st * VS_FLOATS;
#pragma unroll
        for (int i = 0; i < 4; i++) {
            int c = tid + 256 * i;       // 0..1023
            int r = c >> 4, u = c & 15;
            cp_async16(kd + r * KS_STRIDE + u * 4, Kt + (size_t)r * D_MODEL + u * 4);
            cp_async16(vd + r * VS_STRIDE + u * 4, Vt + (size_t)r * D_MODEL + u * 4);
        }
        cp_commit();
    };

    float m0 = -1e30f, m1 = -1e30f, l0 = 0.0f, l1 = 0.0f;
    float oacc[8][4];
#pragma unroll
    for (int dt = 0; dt < 8; dt++)
#pragma unroll
        for (int r = 0; r < 4; r++) oacc[dt][r] = 0.0f;

    load_kv(0, 0);
    load_kv(1, 1);
    cp_wait1();
    __syncthreads();

    const int NKT = SEQ / 64;
    for (int kt = 0; kt < NKT; kt++) {
        const float* kd = Ks + (kt & 1) * KS_FLOATS;
        const float* vd = Vs + (kt & 1) * VS_FLOATS;

        // ---- S = Q @ K^T ----
        float sacc[8][4];
#pragma unroll
        for (int nt = 0; nt < 8; nt++) {
            sacc[nt][0] = 0.0f; sacc[nt][1] = 0.0f;
            sacc[nt][2] = 0.0f; sacc[nt][3] = 0.0f;
#pragma unroll
            for (int k8 = 0; k8 < 8; k8++) {
                uint32_t b0 = __float_as_uint(
                    kd[(nt * 8 + (lane >> 2)) * KS_STRIDE + k8 * 8 + (lane & 3)]);
                uint32_t b1 = __float_as_uint(
                    kd[(nt * 8 + (lane >> 2)) * KS_STRIDE + k8 * 8 + (lane & 3) + 4]);
                mma_tf32(sacc[nt], qf[k8], b0, b1);
            }
        }

        // ---- online softmax (base 2) ----
        float mx0 = -1e30f, mx1 = -1e30f;
#pragma unroll
        for (int nt = 0; nt < 8; nt++) {
            mx0 = fmaxf(mx0, fmaxf(sacc[nt][0], sacc[nt][1]));
            mx1 = fmaxf(mx1, fmaxf(sacc[nt][2], sacc[nt][3]));
        }
        mx0 = fmaxf(mx0, __shfl_xor_sync(0xffffffffu, mx0, 1));
        mx0 = fmaxf(mx0, __shfl_xor_sync(0xffffffffu, mx0, 2));
        mx1 = fmaxf(mx1, __shfl_xor_sync(0xffffffffu, mx1, 1));
        mx1 = fmaxf(mx1, __shfl_xor_sync(0xffffffffu, mx1, 2));
        float mn0 = fmaxf(m0, mx0), mn1 = fmaxf(m1, mx1);
        float sc0 = exp2p(m0 - mn0), sc1 = exp2p(m1 - mn1);
        m0 = mn0; m1 = mn1;

        const int prow0 = wid * 16 + (lane >> 2);
        const int swl   = lane >> 2;          // == prow0 & 7 == prow1 & 7
        float rs0 = 0.0f, rs1 = 0.0f;
#pragma unroll
        for (int nt = 0; nt < 8; nt++) {
            float p0 = exp2p(sacc[nt][0] - mn0);
            float p1 = exp2p(sacc[nt][1] - mn0);
            float p2 = exp2p(sacc[nt][2] - mn1);
            float p3 = exp2p(sacc[nt][3] - mn1);
            rs0 += p0 + p1;
            rs1 += p2 + p3;
            int u  = (nt * 2 + ((lane & 3) >> 1)) ^ swl;
            int fo = (u << 2) + 2 * (lane & 1);
            *(float2*)(Ps + prow0 * 64 + fo) = make_float2(
                __uint_as_float(f2tf32(p0)), __uint_as_float(f2tf32(p1)));
            *(float2*)(Ps + (prow0 + 8) * 64 + fo) = make_float2(
                __uint_as_float(f2tf32(p2)), __uint_as_float(f2tf32(p3)));
        }
        rs0 += __shfl_xor_sync(0xffffffffu, rs0, 1);
        rs0 += __shfl_xor_sync(0xffffffffu, rs0, 2);
        rs1 += __shfl_xor_sync(0xffffffffu, rs1, 1);
        rs1 += __shfl_xor_sync(0xffffffffu, rs1, 2);
        l0 = l0 * sc0 + rs0;
        l1 = l1 * sc1 + rs1;
#pragma unroll
        for (int dt = 0; dt < 8; dt++) {
            oacc[dt][0] *= sc0; oacc[dt][1] *= sc0;
            oacc[dt][2] *= sc1; oacc[dt][3] *= sc1;
        }
        __syncwarp();

        // ---- P fragments via ldmatrix ----
        uint32_t pf[8][4];
#pragma unroll
        for (int pk8 = 0; pk8 < 8; pk8++) {
            int mat = lane >> 3;
            int row = wid * 16 + (lane & 7) + (mat & 1) * 8;
            int u   = pk8 * 2 + (mat >> 1);
            uint32_t addr = (uint32_t)__cvta_generic_to_shared(
                Ps + row * 64 + ((u ^ (row & 7)) << 2));
            asm volatile(
                "ldmatrix.sync.aligned.m8n8.x4.shared.b16 {%0,%1,%2,%3}, [%4];"
                : "=r"(pf[pk8][0]), "=r"(pf[pk8][1]), "=r"(pf[pk8][2]), "=r"(pf[pk8][3])
                : "r"(addr));
        }

        // ---- O += P @ V ----
#pragma unroll
        for (int dt = 0; dt < 8; dt++) {
#pragma unroll
            for (int pk8 = 0; pk8 < 8; pk8++) {
                uint32_t b0 = __float_as_uint(
                    vd[(pk8 * 8 + (lane & 3)) * VS_STRIDE + dt * 8 + (lane >> 2)]);
                uint32_t b1 = __float_as_uint(
                    vd[(pk8 * 8 + (lane & 3) + 4) * VS_STRIDE + dt * 8 + (lane >> 2)]);
                mma_tf32(oacc[dt], pf[pk8], b0, b1);
            }
        }

        __syncthreads();                       // everyone done reading stage kt&1
        if (kt + 2 < NKT) load_kv(kt + 2, kt & 1);
        else cp_commit();
        cp_wait1();                            // (kt+1)'s tile landed
        __syncthreads();
    }

    // ---- normalize + write (tf32-rounded for O-proj consumption) ----
    float inv0 = 1.0f / l0, inv1 = 1.0f / l1;
    const size_t row0 = (size_t)(b * SEQ + qr + (lane >> 2));
#pragma unroll
    for (int dt = 0; dt < 8; dt++) {
        int col = h * HDIM + dt * 8 + 2 * (lane & 3);
        *(float2*)(O + row0 * D_MODEL + col) = make_float2(
            __uint_as_float(f2tf32(oacc[dt][0] * inv0)),
            __uint_as_float(f2tf32(oacc[dt][1] * inv0)));
        *(float2*)(O + (row0 + 8) * D_MODEL + col) = make_float2(
            __uint_as_float(f2tf32(oacc[dt][2] * inv1)),
            __uint_as_float(f2tf32(oacc[dt][3] * inv1)));
    }
}

// ---------------------------------------------------------------------------
// Fused residual add + LayerNorm; optional second tf32-rounded output
// ---------------------------------------------------------------------------
__global__ void __launch_bounds__(256) add_ln_kernel(
    const float* __restrict__ A, const float* __restrict__ R,
    const float* __restrict__ g, const float* __restrict__ beta,
    float* __restrict__ out, float* __restrict__ out_t)
{
    const int row = blockIdx.x;
    const int t   = threadIdx.x;

    float4 a = *(const float4*)(A + (size_t)row * D_MODEL + t * 4);
    float4 r = *(const float4*)(R + (size_t)row * D_MODEL + t * 4);
    float x0 = a.x + r.x, x1 = a.y + r.y, x2 = a.z + r.z, x3 = a.w + r.w;

    float sum = x0 + x1 + x2 + x3;
    float sq  = x0 * x0 + x1 * x1 + x2 * x2 + x3 * x3;

#pragma unroll
    for (int w = 16; w >= 1; w >>= 1) {
        sum += __shfl_xor_sync(0xffffffffu, sum, w);
        sq  += __shfl_xor_sync(0xffffffffu, sq, w);
    }
    __shared__ float ssum[8], ssq[8];
    __shared__ float s_mu, s_rstd;
    if ((t & 31) == 0) {
        ssum[t >> 5] = sum;
        ssq[t >> 5]  = sq;
    }
    __syncthreads();
    if (t == 0) {
        float S = 0.0f, Q = 0.0f;
#pragma unroll
        for (int i = 0; i < 8; i++) { S += ssum[i]; Q += ssq[i]; }
        float mu  = S * (1.0f / D_MODEL);
        float var = Q * (1.0f / D_MODEL) - mu * mu;
        s_mu   = mu;
        s_rstd = rsqrtf(var + 1e-5f);
    }
    __syncthreads();
    float mu = s_mu, rstd = s_rstd;

    float4 gg = *(const float4*)(g + t * 4);
    float4 bb = *(const float4*)(beta + t * 4);
    float4 ov;
    ov.x = (x0 - mu) * rstd * gg.x + bb.x;
    ov.y = (x1 - mu) * rstd * gg.y + bb.y;
    ov.z = (x2 - mu) * rstd * gg.z + bb.z;
    ov.w = (x3 - mu) * rstd * gg.w + bb.w;
    *(float4*)(out + (size_t)row * D_MODEL + t * 4) = ov;
    if (out_t) {
        float4 tv;
        tv.x = __uint_as_float(f2tf32(ov.x));
        tv.y = __uint_as_float(f2tf32(ov.y));
        tv.z = __uint_as_float(f2tf32(ov.z));
        tv.w = __uint_as_float(f2tf32(ov.w));
        *(float4*)(out_t + (size_t)row * D_MODEL + t * 4) = tv;
    }
}

// ---------------------------------------------------------------------------
extern "C" void kernel_launch(void* const* d_in, const int* in_sizes, int n_in,
                              void* d_out, int out_size)
{
    (void)in_sizes; (void)n_in; (void)out_size;

    const float* x     = (const float*)d_in[0];
    const float* w_q   = (const float*)d_in[1];
    const float* b_q   = (const float*)d_in[2];
    const float* w_k   = (const float*)d_in[3];
    const float* b_k   = (const float*)d_in[4];
    const float* w_v   = (const float*)d_in[5];
    const float* b_v   = (const float*)d_in[6];
    const float* w_o   = (const float*)d_in[7];
    const float* b_o   = (const float*)d_in[8];
    const float* w_ff1 = (const float*)d_in[9];
    const float* b_ff1 = (const float*)d_in[10];
    const float* w_ff2 = (const float*)d_in[11];
    const float* b_ff2 = (const float*)d_in[12];
    const float* ln1_g = (const float*)d_in[13];
    const float* ln1_b = (const float*)d_in[14];
    const float* ln2_g = (const float*)d_in[15];
    const float* ln2_b = (const float*)d_in[16];
    float* out = (float*)d_out;

    float *q, *k, *v, *ctx, *t1, *h, *ht, *ff;
    float *xt, *wqt, *wkt, *wvt, *wot, *ff1t, *ff2t;
    cudaGetSymbolAddress((void**)&q,    g_q);
    cudaGetSymbolAddress((void**)&k,    g_k);
    cudaGetSymbolAddress((void**)&v,    g_v);
    cudaGetSymbolAddress((void**)&ctx,  g_ctx);
    cudaGetSymbolAddress((void**)&t1,   g_t1);
    cudaGetSymbolAddress((void**)&h,    g_h);
    cudaGetSymbolAddress((void**)&ht,   g_ht);
    cudaGetSymbolAddress((void**)&ff,   g_ff);
    cudaGetSymbolAddress((void**)&xt,   g_xt);
    cudaGetSymbolAddress((void**)&wqt,  g_wqt);
    cudaGetSymbolAddress((void**)&wkt,  g_wkt);
    cudaGetSymbolAddress((void**)&wvt,  g_wvt);
    cudaGetSymbolAddress((void**)&wot,  g_wot);
    cudaGetSymbolAddress((void**)&ff1t, g_ff1t);
    cudaGetSymbolAddress((void**)&ff2t, g_ff2t);

    cudaFuncSetAttribute(attention_mma_kernel,
                         cudaFuncAttributeMaxDynamicSharedMemorySize, ATT_SMEM_BYTES);
    cudaFuncSetAttribute(qkv_tf32_kernel,
                         cudaFuncAttributeMaxDynamicSharedMemorySize, GEMM_SMEM_BYTES);
    cudaFuncSetAttribute(gemm_tf32_kernel<false, false>,
                         cudaFuncAttributeMaxDynamicSharedMemorySize, GEMM_SMEM_BYTES);
    cudaFuncSetAttribute(gemm_tf32_kernel<true, true>,
                         cudaFuncAttributeMaxDynamicSharedMemorySize, GEMM_SMEM_BYTES);

    dim3 blk(256);

    // -- prepass: tf32-round x and all weights --
    auto roundN = [&](const float* s, float* d, int n) {
        round_tf32_kernel<<<(n / 4 + 255) / 256, 256>>>(
            (const float4*)s, (float4*)d, n / 4);
    };
    roundN(x,     xt,   NTOK * D_MODEL);
    roundN(w_q,   wqt,  D_MODEL * D_MODEL);
    roundN(w_k,   wkt,  D_MODEL * D_MODEL);
    roundN(w_v,   wvt,  D_MODEL * D_MODEL);
    roundN(w_o,   wot,  D_MODEL * D_MODEL);
    roundN(w_ff1, ff1t, D_MODEL * D_FF);
    roundN(w_ff2, ff2t, D_FF * D_MODEL);

    // QKV projections (fused, outputs tf32-rounded)
    qkv_tf32_kernel<<<dim3(D_MODEL / 128, NTOK / 128, 3), blk, GEMM_SMEM_BYTES>>>(
        xt, wqt, b_q, wkt, b_k, wvt, b_v, q, k, v, D_MODEL, D_MODEL);

    // fused tensor-core attention -> ctx (tf32-rounded)
    attention_mma_kernel<<<dim3(SEQ / 128, BATCH * NHEAD), blk, ATT_SMEM_BYTES>>>(
        q, k, v, ctx);

    // output projection (fp32 out, residual only)
    gemm_tf32_kernel<false, false><<<dim3(D_MODEL / 128, NTOK / 128), blk, GEMM_SMEM_BYTES>>>(
        ctx, wot, b_o, t1, D_MODEL, D_MODEL);

    // AddNorm1 -> h (fp32) + ht (tf32)
    add_ln_kernel<<<NTOK, 256>>>(x, t1, ln1_g, ln1_b, h, ht);

    // FFN
    gemm_tf32_kernel<true, true><<<dim3(D_FF / 128, NTOK / 128), blk, GEMM_SMEM_BYTES>>>(
        ht, ff1t, b_ff1, ff, D_MODEL, D_FF);
    gemm_tf32_kernel<false, false><<<dim3(D_MODEL / 128, NTOK / 128), blk, GEMM_SMEM_BYTES>>>(
        ff, ff2t, b_ff2, t1, D_FF, D_MODEL);

    // AddNorm2 -> output (fp32 only)
    add_ln_kernel<<<NTOK, 256>>>(h, t1, ln2_g, ln2_b, out, nullptr);
}

// round 5
// speedup vs baseline: 6.6189x; 1.8197x over previous
#include <cuda_runtime.h>
#include <cuda_fp16.h>
#include <math.h>
#include <stdint.h>

#define D_MODEL 1024
#define D_FF    4096
#define SEQ     2048
#define BATCH   2
#define NTOK    (BATCH*SEQ)   // 4096
#define NHEAD   16
#define HDIM    64

// ---------------- scratch (device globals; no allocation allowed) ----------
__device__ __half g_qh  [NTOK * D_MODEL];
__device__ __half g_kh  [NTOK * D_MODEL];
__device__ __half g_vh  [NTOK * D_MODEL];
__device__ __half g_ctxh[NTOK * D_MODEL];
__device__ float  g_t1  [NTOK * D_MODEL];
__device__ float  g_h   [NTOK * D_MODEL];
__device__ __half g_hh  [NTOK * D_MODEL];
__device__ __half g_ffh [NTOK * D_FF];
// half copies of inputs/weights
__device__ __half g_xh  [NTOK * D_MODEL];
__device__ __half g_wqh [D_MODEL * D_MODEL];
__device__ __half g_wkh [D_MODEL * D_MODEL];
__device__ __half g_wvh [D_MODEL * D_MODEL];
__device__ __half g_woh [D_MODEL * D_MODEL];
__device__ __half g_ff1h[D_MODEL * D_FF];
__device__ __half g_ff2h[D_FF * D_MODEL];

// ---------------------------------------------------------------------------
__device__ __forceinline__ void cp_async16(void* smem_dst, const void* gmem_src) {
    uint32_t da = (uint32_t)__cvta_generic_to_shared(smem_dst);
    asm volatile("cp.async.cg.shared.global [%0], [%1], 16;\n" :: "r"(da), "l"(gmem_src));
}
__device__ __forceinline__ void cp_commit() {
    asm volatile("cp.async.commit_group;\n");
}
__device__ __forceinline__ void cp_wait1() {
    asm volatile("cp.async.wait_group 1;\n");
}
__device__ __forceinline__ void mma_f16(float* c, const uint32_t* a,
                                        uint32_t b0, uint32_t b1) {
    asm volatile(
        "mma.sync.aligned.m16n8k16.row.col.f32.f16.f16.f32 "
        "{%0,%1,%2,%3}, {%4,%5,%6,%7}, {%8,%9}, {%0,%1,%2,%3};"
        : "+f"(c[0]), "+f"(c[1]), "+f"(c[2]), "+f"(c[3])
        : "r"(a[0]), "r"(a[1]), "r"(a[2]), "r"(a[3]), "r"(b0), "r"(b1));
}
#define LDSM_X4(r0, r1, r2, r3, addr) \
    asm volatile("ldmatrix.sync.aligned.m8n8.x4.shared.b16 {%0,%1,%2,%3}, [%4];" \
        : "=r"(r0), "=r"(r1), "=r"(r2), "=r"(r3) : "r"(addr))
#define LDSM_X4T(r0, r1, r2, r3, addr) \
    asm volatile("ldmatrix.sync.aligned.m8n8.x4.trans.shared.b16 {%0,%1,%2,%3}, [%4];" \
        : "=r"(r0), "=r"(r1), "=r"(r2), "=r"(r3) : "r"(addr))

// fast exp2 on the FMA pipe (x <= 0), rel err ~2e-6
__device__ __forceinline__ float exp2p(float x) {
    x = fmaxf(x, -126.0f);
    float z = x + 12582912.0f;
    float f = x - (z - 12582912.0f);
    float p =            1.3333558146e-3f;
    p = fmaf(p, f, 9.6181291918e-3f);
    p = fmaf(p, f, 5.5504108664e-2f);
    p = fmaf(p, f, 2.4022650695e-1f);
    p = fmaf(p, f, 6.9314718056e-1f);
    p = fmaf(p, f, 1.0f);
    return __int_as_float((__float_as_int(z) << 23) + __float_as_int(p));
}

// ===========================================================================
// Prepass: convert x + 6 weight tensors fp32 -> fp16 in ONE launch.
// ===========================================================================
#define R_N0 (NTOK * D_MODEL / 4)
#define R_N1 (D_MODEL * D_MODEL / 4)
#define R_N2 (D_MODEL * D_FF / 4)
#define R_TOTAL (R_N0 + 4 * R_N1 + 2 * R_N2)

__global__ void __launch_bounds__(256) conv_all_kernel(
    const float4* __restrict__ x,   __half* __restrict__ xh,
    const float4* __restrict__ wq,  __half* __restrict__ wqh,
    const float4* __restrict__ wk,  __half* __restrict__ wkh,
    const float4* __restrict__ wv,  __half* __restrict__ wvh,
    const float4* __restrict__ wo,  __half* __restrict__ woh,
    const float4* __restrict__ f1,  __half* __restrict__ f1h,
    const float4* __restrict__ f2,  __half* __restrict__ f2h)
{
    int i = blockIdx.x * 256 + threadIdx.x;
    if (i >= R_TOTAL) return;
    const float4* s; __half* d; int off;
    if      (i < R_N0)                 { s = x;  d = xh;  off = 0; }
    else if (i < R_N0 + R_N1)          { s = wq; d = wqh; off = R_N0; }
    else if (i < R_N0 + 2*R_N1)        { s = wk; d = wkh; off = R_N0 + R_N1; }
    else if (i < R_N0 + 3*R_N1)        { s = wv; d = wvh; off = R_N0 + 2*R_N1; }
    else if (i < R_N0 + 4*R_N1)        { s = wo; d = woh; off = R_N0 + 3*R_N1; }
    else if (i < R_N0 + 4*R_N1 + R_N2) { s = f1; d = f1h; off = R_N0 + 4*R_N1; }
    else                               { s = f2; d = f2h; off = R_N0 + 4*R_N1 + R_N2; }
    int j = i - off;
    float4 v = s[j];
    __half2 h0 = __floats2half2_rn(v.x, v.y);
    __half2 h1 = __floats2half2_rn(v.z, v.w);
    uint2 pk;
    pk.x = *(uint32_t*)&h0;
    pk.y = *(uint32_t*)&h1;
    *(uint2*)(d + (size_t)j * 4) = pk;
}

// ===========================================================================
// fp16 tensor-core GEMM: C[N,M] = A[N,K] @ W[K,M] + bias (+ReLU)(*oscale)
// CTA 128x128, BK=64, 3-stage cp.async, 8 warps (2x4), warp tile 64x32.
// A smem: [m][k] 128B rows, xor-swizzled (ldmatrix.x4).
// B smem: [k][n] rows padded to 272B (ldmatrix.x4.trans, conflict-free).
// ===========================================================================
#define GA_BYTES 16384              // 128 rows * 128B
#define GB_PITCH 272                // 128 halves + 8 pad, bytes
#define GB_BYTES (64 * GB_PITCH)    // 17408
#define G_STAGE  (GA_BYTES + GB_BYTES)
#define G_SMEM   (3 * G_STAGE)      // 101376

template <bool RELU, bool OUTH>
__device__ __forceinline__ void gemm_h_body(
    const __half* __restrict__ A, const __half* __restrict__ W,
    const float* __restrict__ bias, void* __restrict__ Cout,
    int K, int M, int row0, int col0, float oscale)
{
    extern __shared__ char smem[];
    const int tid  = threadIdx.x;
    const int lane = tid & 31;
    const int wid  = tid >> 5;
    const int warp_m = wid & 1;
    const int warp_n = wid >> 1;
    const uint32_t sbase = (uint32_t)__cvta_generic_to_shared(smem);

    float acc[4][4][4];
#pragma unroll
    for (int mt = 0; mt < 4; mt++)
#pragma unroll
        for (int nt = 0; nt < 4; nt++)
#pragma unroll
            for (int r = 0; r < 4; r++) acc[mt][nt][r] = 0.0f;

    const int KT = K / 64;

    auto load_stage = [&](int kt) {
        char* base = smem + (kt % 3) * G_STAGE;
        const int k0 = kt * 64;
#pragma unroll
        for (int i = 0; i < 4; i++) {           // A: 1024 x 16B
            int c = tid + 256 * i;
            int r = c >> 3, u = c & 7;
            cp_async16(base + r * 128 + (((u ^ (r & 7))) << 4),
                       A + (size_t)(row0 + r) * K + k0 + u * 8);
        }
#pragma unroll
        for (int i = 0; i < 4; i++) {           // B: 1024 x 16B
            int c = tid + 256 * i;
            int k = c >> 4, u = c & 15;
            cp_async16(base + GA_BYTES + k * GB_PITCH + u * 16,
                       W + (size_t)(k0 + k) * M + col0 + u * 8);
        }
        cp_commit();
    };

    load_stage(0);
    load_stage(1);

    for (int kt = 0; kt < KT; kt++) {
        cp_wait1();
        __syncthreads();
        if (kt + 2 < KT) load_stage(kt + 2);
        else cp_commit();

        const uint32_t ab = sbase + (uint32_t)((kt % 3) * G_STAGE);
        const uint32_t bb = ab + GA_BYTES;

#pragma unroll
        for (int k16 = 0; k16 < 4; k16++) {
            uint32_t a[4][4];
#pragma unroll
            for (int mt = 0; mt < 4; mt++) {
                int m = warp_m * 64 + mt * 16 + (lane & 7) + ((lane >> 3) & 1) * 8;
                int u = k16 * 2 + (lane >> 4);
                LDSM_X4(a[mt][0], a[mt][1], a[mt][2], a[mt][3],
                        ab + m * 128 + ((u ^ (m & 7)) << 4));
            }
            uint32_t b[4][2];
#pragma unroll
            for (int ng = 0; ng < 2; ng++) {
                int k    = k16 * 16 + (lane & 7) + ((lane >> 3) & 1) * 8;
                int noff = warp_n * 32 + ng * 16 + ((lane >> 4) & 1) * 8;
                LDSM_X4T(b[ng*2][0], b[ng*2][1], b[ng*2+1][0], b[ng*2+1][1],
                         bb + k * GB_PITCH + noff * 2);
            }
#pragma unroll
            for (int mt = 0; mt < 4; mt++)
#pragma unroll
                for (int nt = 0; nt < 4; nt++)
                    mma_f16(acc[mt][nt], a[mt], b[nt][0], b[nt][1]);
        }
        __syncthreads();
    }

    // ---- epilogue ----
#pragma unroll
    for (int nt = 0; nt < 4; nt++) {
        int ncol = col0 + warp_n * 32 + nt * 8 + (lane & 3) * 2;
        float bj0 = bias[ncol];
        float bj1 = bias[ncol + 1];
#pragma unroll
        for (int mt = 0; mt < 4; mt++) {
            int r0 = row0 + warp_m * 64 + mt * 16 + (lane >> 2);
            float v0 = (acc[mt][nt][0] + bj0) * oscale;
            float v1 = (acc[mt][nt][1] + bj1) * oscale;
            float v2 = (acc[mt][nt][2] + bj0) * oscale;
            float v3 = (acc[mt][nt][3] + bj1) * oscale;
            if (RELU) {
                v0 = fmaxf(v0, 0.0f); v1 = fmaxf(v1, 0.0f);
                v2 = fmaxf(v2, 0.0f); v3 = fmaxf(v3, 0.0f);
            }
            if (OUTH) {
                __half* Ch = (__half*)Cout;
                __half2 h0 = __floats2half2_rn(v0, v1);
                __half2 h1 = __floats2half2_rn(v2, v3);
                *(__half2*)(Ch + (size_t)r0 * M + ncol)       = h0;
                *(__half2*)(Ch + (size_t)(r0 + 8) * M + ncol) = h1;
            } else {
                float* Cf = (float*)Cout;
                *(float2*)(Cf + (size_t)r0 * M + ncol)       = make_float2(v0, v1);
                *(float2*)(Cf + (size_t)(r0 + 8) * M + ncol) = make_float2(v2, v3);
            }
        }
    }
}

template <bool RELU, bool OUTH>
__global__ void __launch_bounds__(256) gemm_h_kernel(
    const __half* __restrict__ A, const __half* __restrict__ W,
    const float* __restrict__ bias, void* __restrict__ Cout, int K, int M)
{
    gemm_h_body<RELU, OUTH>(A, W, bias, Cout, K, M,
                            blockIdx.y * 128, blockIdx.x * 128, 1.0f);
}

#define QSCALE (0.125f * 1.4426950408889634f)   // 1/sqrt(64) * log2(e)

__global__ void __launch_bounds__(256) qkv_h_kernel(
    const __half* __restrict__ x,
    const __half* __restrict__ wq, const float* __restrict__ bq,
    const __half* __restrict__ wk, const float* __restrict__ bk,
    const __half* __restrict__ wv, const float* __restrict__ bv,
    __half* __restrict__ q, __half* __restrict__ k, __half* __restrict__ v,
    int K, int M)
{
    const int z = blockIdx.z;
    const __half* W    = (z == 0) ? wq : (z == 1) ? wk : wv;
    const float*  bias = (z == 0) ? bq : (z == 1) ? bk : bv;
    __half*       C    = (z == 0) ? q  : (z == 1) ? k  : v;
    float oscale = (z == 0) ? QSCALE : 1.0f;
    gemm_h_body<false, true>(x, W, bias, C, K, M,
                             blockIdx.y * 128, blockIdx.x * 128, oscale);
}

// ===========================================================================
// Flash attention, fp16 mma.sync m16n8k16, base-2 online softmax.
// CTA = (b,h) x 128 q rows; 8 warps x 16 q rows. K/V 64x64 double-buffered.
// K smem: [j][d] rows padded to 144B (scalar LDS b-frags, conflict-free).
// V smem: [j][d] rows padded to 144B (ldmatrix.x4.trans).
// P smem: [q][j] 128B rows, xor-swizzled (ldmatrix.x4).
// ===========================================================================
#define AK_PITCH 144
#define AK_BYTES (64 * AK_PITCH)     // 9216 per stage
#define AP_OFF   (4 * AK_BYTES)      // 36864
#define ATT_SMEM (AP_OFF + 128 * 128)  // + P 16384 = 53248

__global__ void __launch_bounds__(256, 1) attention_h_kernel(
    const __half* __restrict__ Q, const __half* __restrict__ K,
    const __half* __restrict__ V, __half* __restrict__ O)
{
    extern __shared__ char smem[];
    const uint32_t sbase = (uint32_t)__cvta_generic_to_shared(smem);

    const int tid  = threadIdx.x;
    const int lane = tid & 31;
    const int wid  = tid >> 5;
    const int b    = blockIdx.y >> 4;
    const int h    = blockIdx.y & 15;
    const int qr   = blockIdx.x * 128 + wid * 16;

    const __half* Qb = Q + ((size_t)(b * SEQ + qr)) * D_MODEL + h * HDIM;
    const __half* Kb = K + ((size_t)(b * SEQ)) * D_MODEL + h * HDIM;
    const __half* Vb = V + ((size_t)(b * SEQ)) * D_MODEL + h * HDIM;

    // Q fragments resident in registers (q already scaled by QSCALE)
    uint32_t qf[4][4];
    {
        const int r = lane >> 2, c2 = (lane & 3) * 2;
#pragma unroll
        for (int k16 = 0; k16 < 4; k16++) {
            qf[k16][0] = *(const uint32_t*)(Qb + (size_t)r * D_MODEL + k16 * 16 + c2);
            qf[k16][1] = *(const uint32_t*)(Qb + (size_t)(r + 8) * D_MODEL + k16 * 16 + c2);
            qf[k16][2] = *(const uint32_t*)(Qb + (size_t)r * D_MODEL + k16 * 16 + c2 + 8);
            qf[k16][3] = *(const uint32_t*)(Qb + (size_t)(r + 8) * D_MODEL + k16 * 16 + c2 + 8);
        }
    }

    auto load_kv = [&](int kt, int st) {
        const __half* Kt = Kb + (size_t)kt * 64 * D_MODEL;
        const __half* Vt = Vb + (size_t)kt * 64 * D_MODEL;
        char* kd = smem + st * AK_BYTES;
        char* vd = smem + (2 + st) * AK_BYTES;
#pragma unroll
        for (int i = 0; i < 2; i++) {
            int c = tid + 256 * i;          // 0..511
            int r = c >> 3, u = c & 7;
            cp_async16(kd + r * AK_PITCH + u * 16, Kt + (size_t)r * D_MODEL + u * 8);
            cp_async16(vd + r * AK_PITCH + u * 16, Vt + (size_t)r * D_MODEL + u * 8);
        }
        cp_commit();
    };

    float m0 = -1e30f, m1 = -1e30f, l0 = 0.0f, l1 = 0.0f;
    float oacc[8][4];
#pragma unroll
    for (int dt = 0; dt < 8; dt++)
#pragma unroll
        for (int r = 0; r < 4; r++) oacc[dt][r] = 0.0f;

    load_kv(0, 0);
    load_kv(1, 1);
    cp_wait1();
    __syncthreads();

    const int NKT = SEQ / 64;
    for (int kt = 0; kt < NKT; kt++) {
        const __half* kd = (const __half*)(smem + (kt & 1) * AK_BYTES);
        const uint32_t vdb = sbase + (uint32_t)((2 + (kt & 1)) * AK_BYTES);

        // ---- S = Q @ K^T ----
        float sacc[8][4];
#pragma unroll
        for (int nt = 0; nt < 8; nt++) {
            sacc[nt][0] = 0.0f; sacc[nt][1] = 0.0f;
            sacc[nt][2] = 0.0f; sacc[nt][3] = 0.0f;
            const int j = nt * 8 + (lane >> 2);
#pragma unroll
            for (int k16 = 0; k16 < 4; k16++) {
                int idx = j * 72 + k16 * 16 + (lane & 3) * 2;
                uint32_t b0 = *(const uint32_t*)(kd + idx);
                uint32_t b1 = *(const uint32_t*)(kd + idx + 8);
                mma_f16(sacc[nt], qf[k16], b0, b1);
            }
        }

        // ---- online softmax (base 2, scale pre-folded into Q) ----
        float mx0 = -1e30f, mx1 = -1e30f;
#pragma unroll
        for (int nt = 0; nt < 8; nt++) {
            mx0 = fmaxf(mx0, fmaxf(sacc[nt][0], sacc[nt][1]));
            mx1 = fmaxf(mx1, fmaxf(sacc[nt][2], sacc[nt][3]));
        }
        mx0 = fmaxf(mx0, __shfl_xor_sync(0xffffffffu, mx0, 1));
        mx0 = fmaxf(mx0, __shfl_xor_sync(0xffffffffu, mx0, 2));
        mx1 = fmaxf(mx1, __shfl_xor_sync(0xffffffffu, mx1, 1));
        mx1 = fmaxf(mx1, __shfl_xor_sync(0xffffffffu, mx1, 2));
        float mn0 = fmaxf(m0, mx0), mn1 = fmaxf(m1, mx1);
        float sc0 = exp2p(m0 - mn0), sc1 = exp2p(m1 - mn1);
        m0 = mn0; m1 = mn1;

        const int prow = wid * 16 + (lane >> 2);
        char* Pb = smem + AP_OFF;
        float rs0 = 0.0f, rs1 = 0.0f;
#pragma unroll
        for (int nt = 0; nt < 8; nt++) {
            float p0 = exp2p(sacc[nt][0] - mn0);
            float p1 = exp2p(sacc[nt][1] - mn0);
            float p2 = exp2p(sacc[nt][2] - mn1);
            float p3 = exp2p(sacc[nt][3] - mn1);
            rs0 += p0 + p1;
            rs1 += p2 + p3;
            __half2 hp0 = __floats2half2_rn(p0, p1);
            __half2 hp1 = __floats2half2_rn(p2, p3);
            int bo = ((nt ^ (prow & 7)) << 4) + (lane & 3) * 4;
            *(__half2*)(Pb + prow * 128 + bo)       = hp0;
            *(__half2*)(Pb + (prow + 8) * 128 + bo) = hp1;
        }
        rs0 += __shfl_xor_sync(0xffffffffu, rs0, 1);
        rs0 += __shfl_xor_sync(0xffffffffu, rs0, 2);
        rs1 += __shfl_xor_sync(0xffffffffu, rs1, 1);
        rs1 += __shfl_xor_sync(0xffffffffu, rs1, 2);
        l0 = l0 * sc0 + rs0;
        l1 = l1 * sc1 + rs1;
#pragma unroll
        for (int dt = 0; dt < 8; dt++) {
            oacc[dt][0] *= sc0; oacc[dt][1] *= sc0;
            oacc[dt][2] *= sc1; oacc[dt][3] *= sc1;
        }
        __syncwarp();

        // ---- O += P @ V ----
        const uint32_t pbb = sbase + AP_OFF;
#pragma unroll
        for (int k16 = 0; k16 < 4; k16++) {
            uint32_t pf[4];
            {
                int row = wid * 16 + (lane & 7) + ((lane >> 3) & 1) * 8;
                int u   = k16 * 2 + (lane >> 4);
                LDSM_X4(pf[0], pf[1], pf[2], pf[3],
                        pbb + row * 128 + ((u ^ (row & 7)) << 4));
            }
            uint32_t vb[8][2];
#pragma unroll
            for (int ng = 0; ng < 4; ng++) {
                int j    = k16 * 16 + (lane & 7) + ((lane >> 3) & 1) * 8;
                int doff = ng * 16 + ((lane >> 4) & 1) * 8;
                LDSM_X4T(vb[ng*2][0], vb[ng*2][1], vb[ng*2+1][0], vb[ng*2+1][1],
                         vdb + j * AK_PITCH + doff * 2);
            }
#pragma unroll
            for (int dt = 0; dt < 8; dt++)
                mma_f16(oacc[dt], pf, vb[dt][0], vb[dt][1]);
        }

        __syncthreads();
        if (kt + 2 < NKT) load_kv(kt + 2, kt & 1);
        else cp_commit();
        cp_wait1();
        __syncthreads();
    }

    // ---- normalize + write ctx (half) ----
    float inv0 = 1.0f / l0, inv1 = 1.0f / l1;
    const size_t row0 = (size_t)(b * SEQ + qr + (lane >> 2));
#pragma unroll
    for (int dt = 0; dt < 8; dt++) {
        int col = h * HDIM + dt * 8 + 2 * (lane & 3);
        __half2 h0 = __floats2half2_rn(oacc[dt][0] * inv0, oacc[dt][1] * inv0);
        __half2 h1 = __floats2half2_rn(oacc[dt][2] * inv1, oacc[dt][3] * inv1);
        *(__half2*)(O + row0 * D_MODEL + col)       = h0;
        *(__half2*)(O + (row0 + 8) * D_MODEL + col) = h1;
    }
}

// ---------------------------------------------------------------------------
// Fused residual add + LayerNorm; optional half output copy
// ---------------------------------------------------------------------------
__global__ void __launch_bounds__(256) add_ln_kernel(
    const float* __restrict__ A, const float* __restrict__ R,
    const float* __restrict__ g, const float* __restrict__ beta,
    float* __restrict__ out, __half* __restrict__ out_h)
{
    const int row = blockIdx.x;
    const int t   = threadIdx.x;

    float4 a = *(const float4*)(A + (size_t)row * D_MODEL + t * 4);
    float4 r = *(const float4*)(R + (size_t)row * D_MODEL + t * 4);
    float x0 = a.x + r.x, x1 = a.y + r.y, x2 = a.z + r.z, x3 = a.w + r.w;

    float sum = x0 + x1 + x2 + x3;
    float sq  = x0 * x0 + x1 * x1 + x2 * x2 + x3 * x3;

#pragma unroll
    for (int w = 16; w >= 1; w >>= 1) {
        sum += __shfl_xor_sync(0xffffffffu, sum, w);
        sq  += __shfl_xor_sync(0xffffffffu, sq, w);
    }
    __shared__ float ssum[8], ssq[8];
    __shared__ float s_mu, s_rstd;
    if ((t & 31) == 0) {
        ssum[t >> 5] = sum;
        ssq[t >> 5]  = sq;
    }
    __syncthreads();
    if (t == 0) {
        float S = 0.0f, Q = 0.0f;
#pragma unroll
        for (int i = 0; i < 8; i++) { S += ssum[i]; Q += ssq[i]; }
        float mu  = S * (1.0f / D_MODEL);
        float var = Q * (1.0f / D_MODEL) - mu * mu;
        s_mu   = mu;
        s_rstd = rsqrtf(var + 1e-5f);
    }
    __syncthreads();
    float mu = s_mu, rstd = s_rstd;

    float4 gg = *(const float4*)(g + t * 4);
    float4 bb = *(const float4*)(beta + t * 4);
    float4 ov;
    ov.x = (x0 - mu) * rstd * gg.x + bb.x;
    ov.y = (x1 - mu) * rstd * gg.y + bb.y;
    ov.z = (x2 - mu) * rstd * gg.z + bb.z;
    ov.w = (x3 - mu) * rstd * gg.w + bb.w;
    *(float4*)(out + (size_t)row * D_MODEL + t * 4) = ov;
    if (out_h) {
        __half2 h0 = __floats2half2_rn(ov.x, ov.y);
        __half2 h1 = __floats2half2_rn(ov.z, ov.w);
        uint2 pk;
        pk.x = *(uint32_t*)&h0;
        pk.y = *(uint32_t*)&h1;
        *(uint2*)(out_h + (size_t)row * D_MODEL + t * 4) = pk;
    }
}

// ---------------------------------------------------------------------------
extern "C" void kernel_launch(void* const* d_in, const int* in_sizes, int n_in,
                              void* d_out, int out_size)
{
    (void)in_sizes; (void)n_in; (void)out_size;

    const float* x     = (const float*)d_in[0];
    const float* w_q   = (const float*)d_in[1];
    const float* b_q   = (const float*)d_in[2];
    const float* w_k   = (const float*)d_in[3];
    const float* b_k   = (const float*)d_in[4];
    const float* w_v   = (const float*)d_in[5];
    const float* b_v   = (const float*)d_in[6];
    const float* w_o   = (const float*)d_in[7];
    const float* b_o   = (const float*)d_in[8];
    const float* w_ff1 = (const float*)d_in[9];
    const float* b_ff1 = (const float*)d_in[10];
    const float* w_ff2 = (const float*)d_in[11];
    const float* b_ff2 = (const float*)d_in[12];
    const float* ln1_g = (const float*)d_in[13];
    const float* ln1_b = (const float*)d_in[14];
    const float* ln2_g = (const float*)d_in[15];
    const float* ln2_b = (const float*)d_in[16];
    float* out = (float*)d_out;

    __half *qh, *kh, *vh, *ctxh, *hh, *ffh;
    __half *xh, *wqh, *wkh, *wvh, *woh, *ff1h, *ff2h;
    float *t1, *h;
    cudaGetSymbolAddress((void**)&qh,   g_qh);
    cudaGetSymbolAddress((void**)&kh,   g_kh);
    cudaGetSymbolAddress((void**)&vh,   g_vh);
    cudaGetSymbolAddress((void**)&ctxh, g_ctxh);
    cudaGetSymbolAddress((void**)&t1,   g_t1);
    cudaGetSymbolAddress((void**)&h,    g_h);
    cudaGetSymbolAddress((void**)&hh,   g_hh);
    cudaGetSymbolAddress((void**)&ffh,  g_ffh);
    cudaGetSymbolAddress((void**)&xh,   g_xh);
    cudaGetSymbolAddress((void**)&wqh,  g_wqh);
    cudaGetSymbolAddress((void**)&wkh,  g_wkh);
    cudaGetSymbolAddress((void**)&wvh,  g_wvh);
    cudaGetSymbolAddress((void**)&woh,  g_woh);
    cudaGetSymbolAddress((void**)&ff1h, g_ff1h);
    cudaGetSymbolAddress((void**)&ff2h, g_ff2h);

    cudaFuncSetAttribute(attention_h_kernel,
                         cudaFuncAttributeMaxDynamicSharedMemorySize, ATT_SMEM);
    cudaFuncSetAttribute(qkv_h_kernel,
                         cudaFuncAttributeMaxDynamicSharedMemorySize, G_SMEM);
    cudaFuncSetAttribute(gemm_h_kernel<false, false>,
                         cudaFuncAttributeMaxDynamicSharedMemorySize, G_SMEM);
    cudaFuncSetAttribute(gemm_h_kernel<true, true>,
                         cudaFuncAttributeMaxDynamicSharedMemorySize, G_SMEM);

    dim3 blk(256);

    // 1) fp32 -> fp16 prepass (single launch)
    conv_all_kernel<<<(R_TOTAL + 255) / 256, blk>>>(
        (const float4*)x, xh,
        (const float4*)w_q, wqh,
        (const float4*)w_k, wkh,
        (const float4*)w_v, wvh,
        (const float4*)w_o, woh,
        (const float4*)w_ff1, ff1h,
        (const float4*)w_ff2, ff2h);

    // 2) QKV projections (fused, grid.z = 3; q pre-scaled by QSCALE)
    qkv_h_kernel<<<dim3(D_MODEL / 128, NTOK / 128, 3), blk, G_SMEM>>>(
        xh, wqh, b_q, wkh, b_k, wvh, b_v, qh, kh, vh, D_MODEL, D_MODEL);

    // 3) flash attention -> ctx (half)
    attention_h_kernel<<<dim3(SEQ / 128, BATCH * NHEAD), blk, ATT_SMEM>>>(
        qh, kh, vh, ctxh);

    // 4) output projection -> t1 (fp32)
    gemm_h_kernel<false, false><<<dim3(D_MODEL / 128, NTOK / 128), blk, G_SMEM>>>(
        ctxh, woh, b_o, t1, D_MODEL, D_MODEL);

    // 5) AddNorm1 -> h (fp32) + hh (half)
    add_ln_kernel<<<NTOK, 256>>>(x, t1, ln1_g, ln1_b, h, hh);

    // 6) FFN1 (ReLU) -> ffh (half)
    gemm_h_kernel<true, true><<<dim3(D_FF / 128, NTOK / 128), blk, G_SMEM>>>(
        hh, ff1h, b_ff1, ffh, D_MODEL, D_FF);

    // 7) FFN2 -> t1 (fp32)
    gemm_h_kernel<false, false><<<dim3(D_MODEL / 128, NTOK / 128), blk, G_SMEM>>>(
        ffh, ff2h, b_ff2, t1, D_FF, D_MODEL);

    // 8) AddNorm2 -> output
    add_ln_kernel<<<NTOK, 256>>>(h, t1, ln2_g, ln2_b, out, nullptr);
}

// round 6
// speedup vs baseline: 6.6389x; 1.0030x over previous
#include <cuda_runtime.h>
#include <cuda_fp16.h>
#include <math.h>
#include <stdint.h>

#define D_MODEL 1024
#define D_FF    4096
#define SEQ     2048
#define BATCH   2
#define NTOK    (BATCH*SEQ)   // 4096
#define NHEAD   16
#define HDIM    64

// ---------------- scratch (device globals; no allocation allowed) ----------
__device__ __half g_qh  [NTOK * D_MODEL];
__device__ __half g_kh  [NTOK * D_MODEL];
__device__ __half g_vh  [NTOK * D_MODEL];
__device__ __half g_ctxh[NTOK * D_MODEL];
__device__ float  g_t1  [NTOK * D_MODEL];
__device__ float  g_h   [NTOK * D_MODEL];
__device__ __half g_hh  [NTOK * D_MODEL];
__device__ __half g_ffh [NTOK * D_FF];
// half copies of inputs/weights
__device__ __half g_xh  [NTOK * D_MODEL];
__device__ __half g_wqh [D_MODEL * D_MODEL];
__device__ __half g_wkh [D_MODEL * D_MODEL];
__device__ __half g_wvh [D_MODEL * D_MODEL];
__device__ __half g_woh [D_MODEL * D_MODEL];
__device__ __half g_ff1h[D_MODEL * D_FF];
__device__ __half g_ff2h[D_FF * D_MODEL];

// ---------------------------------------------------------------------------
__device__ __forceinline__ void cp_async16(void* smem_dst, const void* gmem_src) {
    uint32_t da = (uint32_t)__cvta_generic_to_shared(smem_dst);
    asm volatile("cp.async.cg.shared.global [%0], [%1], 16;\n" :: "r"(da), "l"(gmem_src));
}
__device__ __forceinline__ void cp_commit() {
    asm volatile("cp.async.commit_group;\n");
}
__device__ __forceinline__ void cp_wait1() {
    asm volatile("cp.async.wait_group 1;\n");
}
__device__ __forceinline__ void mma_f16(float* c, const uint32_t* a,
                                        uint32_t b0, uint32_t b1) {
    asm volatile(
        "mma.sync.aligned.m16n8k16.row.col.f32.f16.f16.f32 "
        "{%0,%1,%2,%3}, {%4,%5,%6,%7}, {%8,%9}, {%0,%1,%2,%3};"
        : "+f"(c[0]), "+f"(c[1]), "+f"(c[2]), "+f"(c[3])
        : "r"(a[0]), "r"(a[1]), "r"(a[2]), "r"(a[3]), "r"(b0), "r"(b1));
}
#define LDSM_X4(r0, r1, r2, r3, addr) \
    asm volatile("ldmatrix.sync.aligned.m8n8.x4.shared.b16 {%0,%1,%2,%3}, [%4];" \
        : "=r"(r0), "=r"(r1), "=r"(r2), "=r"(r3) : "r"(addr))
#define LDSM_X4T(r0, r1, r2, r3, addr) \
    asm volatile("ldmatrix.sync.aligned.m8n8.x4.trans.shared.b16 {%0,%1,%2,%3}, [%4];" \
        : "=r"(r0), "=r"(r1), "=r"(r2), "=r"(r3) : "r"(addr))

// fast exp2 on the FMA pipe (x <= 0), rel err ~2e-6
__device__ __forceinline__ float exp2p(float x) {
    x = fmaxf(x, -126.0f);
    float z = x + 12582912.0f;
    float f = x - (z - 12582912.0f);
    float p =            1.3333558146e-3f;
    p = fmaf(p, f, 9.6181291918e-3f);
    p = fmaf(p, f, 5.5504108664e-2f);
    p = fmaf(p, f, 2.4022650695e-1f);
    p = fmaf(p, f, 6.9314718056e-1f);
    p = fmaf(p, f, 1.0f);
    return __int_as_float((__float_as_int(z) << 23) + __float_as_int(p));
}

// ===========================================================================
// Prepass: convert x + 6 weight tensors fp32 -> fp16 in ONE launch.
// ===========================================================================
#define R_N0 (NTOK * D_MODEL / 4)
#define R_N1 (D_MODEL * D_MODEL / 4)
#define R_N2 (D_MODEL * D_FF / 4)
#define R_TOTAL (R_N0 + 4 * R_N1 + 2 * R_N2)

__global__ void __launch_bounds__(256) conv_all_kernel(
    const float4* __restrict__ x,   __half* __restrict__ xh,
    const float4* __restrict__ wq,  __half* __restrict__ wqh,
    const float4* __restrict__ wk,  __half* __restrict__ wkh,
    const float4* __restrict__ wv,  __half* __restrict__ wvh,
    const float4* __restrict__ wo,  __half* __restrict__ woh,
    const float4* __restrict__ f1,  __half* __restrict__ f1h,
    const float4* __restrict__ f2,  __half* __restrict__ f2h)
{
    int i = blockIdx.x * 256 + threadIdx.x;
    if (i >= R_TOTAL) return;
    const float4* s; __half* d; int off;
    if      (i < R_N0)                 { s = x;  d = xh;  off = 0; }
    else if (i < R_N0 + R_N1)          { s = wq; d = wqh; off = R_N0; }
    else if (i < R_N0 + 2*R_N1)        { s = wk; d = wkh; off = R_N0 + R_N1; }
    else if (i < R_N0 + 3*R_N1)        { s = wv; d = wvh; off = R_N0 + 2*R_N1; }
    else if (i < R_N0 + 4*R_N1)        { s = wo; d = woh; off = R_N0 + 3*R_N1; }
    else if (i < R_N0 + 4*R_N1 + R_N2) { s = f1; d = f1h; off = R_N0 + 4*R_N1; }
    else                               { s = f2; d = f2h; off = R_N0 + 4*R_N1 + R_N2; }
    int j = i - off;
    float4 v = s[j];
    __half2 h0 = __floats2half2_rn(v.x, v.y);
    __half2 h1 = __floats2half2_rn(v.z, v.w);
    uint2 pk;
    pk.x = *(uint32_t*)&h0;
    pk.y = *(uint32_t*)&h1;
    *(uint2*)(d + (size_t)j * 4) = pk;
}

// ===========================================================================
// fp16 tensor-core GEMM: C[N,M] = A[N,K] @ W[K,M] + bias (+ReLU)(*oscale)
// CTA 128x128, BK=64, 3-stage cp.async, 4 warps (2x2), warp tile 64x64.
// Per k16 per warp: 8 ldmatrix vs 32 HMMA (4:1) -> tensor-pipe dense.
// A smem: [m][k] 128B rows, xor-swizzled (ldmatrix.x4).
// B smem: [k][n] rows padded to 272B (ldmatrix.x4.trans, conflict-free).
// ===========================================================================
#define GA_BYTES 16384              // 128 rows * 128B
#define GB_PITCH 272                // 128 halves + 8 pad, bytes
#define GB_BYTES (64 * GB_PITCH)    // 17408
#define G_STAGE  (GA_BYTES + GB_BYTES)
#define G_SMEM   (3 * G_STAGE)      // 101376
#define G_THREADS 128

template <bool RELU, bool OUTH>
__device__ __forceinline__ void gemm_h_body(
    const __half* __restrict__ A, const __half* __restrict__ W,
    const float* __restrict__ bias, void* __restrict__ Cout,
    int K, int M, int row0, int col0, float oscale)
{
    extern __shared__ char smem[];
    const int tid  = threadIdx.x;
    const int lane = tid & 31;
    const int wid  = tid >> 5;
    const int warp_m = wid & 1;   // 2 x 64 rows
    const int warp_n = wid >> 1;  // 2 x 64 cols
    const uint32_t sbase = (uint32_t)__cvta_generic_to_shared(smem);

    float acc[4][8][4];
#pragma unroll
    for (int mt = 0; mt < 4; mt++)
#pragma unroll
        for (int nt = 0; nt < 8; nt++)
#pragma unroll
            for (int r = 0; r < 4; r++) acc[mt][nt][r] = 0.0f;

    const int KT = K / 64;

    auto load_stage = [&](int kt) {
        char* base = smem + (kt % 3) * G_STAGE;
        const int k0 = kt * 64;
#pragma unroll
        for (int i = 0; i < 8; i++) {           // A: 1024 x 16B
            int c = tid + G_THREADS * i;
            int r = c >> 3, u = c & 7;
            cp_async16(base + r * 128 + (((u ^ (r & 7))) << 4),
                       A + (size_t)(row0 + r) * K + k0 + u * 8);
        }
#pragma unroll
        for (int i = 0; i < 8; i++) {           // B: 1024 x 16B
            int c = tid + G_THREADS * i;
            int k = c >> 4, u = c & 15;
            cp_async16(base + GA_BYTES + k * GB_PITCH + u * 16,
                       W + (size_t)(k0 + k) * M + col0 + u * 8);
        }
        cp_commit();
    };

    load_stage(0);
    load_stage(1);

    for (int kt = 0; kt < KT; kt++) {
        cp_wait1();
        __syncthreads();
        if (kt + 2 < KT) load_stage(kt + 2);
        else cp_commit();

        const uint32_t ab = sbase + (uint32_t)((kt % 3) * G_STAGE);
        const uint32_t bb = ab + GA_BYTES;

#pragma unroll
        for (int k16 = 0; k16 < 4; k16++) {
            uint32_t a[4][4];
#pragma unroll
            for (int mt = 0; mt < 4; mt++) {
                int m = warp_m * 64 + mt * 16 + (lane & 7) + ((lane >> 3) & 1) * 8;
                int u = k16 * 2 + (lane >> 4);
                LDSM_X4(a[mt][0], a[mt][1], a[mt][2], a[mt][3],
                        ab + m * 128 + ((u ^ (m & 7)) << 4));
            }
            uint32_t b[8][2];
#pragma unroll
            for (int ng = 0; ng < 4; ng++) {
                int k    = k16 * 16 + (lane & 7) + ((lane >> 3) & 1) * 8;
                int noff = warp_n * 64 + ng * 16 + ((lane >> 4) & 1) * 8;
                LDSM_X4T(b[ng*2][0], b[ng*2][1], b[ng*2+1][0], b[ng*2+1][1],
                         bb + k * GB_PITCH + noff * 2);
            }
#pragma unroll
            for (int mt = 0; mt < 4; mt++)
#pragma unroll
                for (int nt = 0; nt < 8; nt++)
                    mma_f16(acc[mt][nt], a[mt], b[nt][0], b[nt][1]);
        }
        __syncthreads();
    }

    // ---- epilogue ----
#pragma unroll
    for (int nt = 0; nt < 8; nt++) {
        int ncol = col0 + warp_n * 64 + nt * 8 + (lane & 3) * 2;
        float bj0 = bias[ncol];
        float bj1 = bias[ncol + 1];
#pragma unroll
        for (int mt = 0; mt < 4; mt++) {
            int r0 = row0 + warp_m * 64 + mt * 16 + (lane >> 2);
            float v0 = (acc[mt][nt][0] + bj0) * oscale;
            float v1 = (acc[mt][nt][1] + bj1) * oscale;
            float v2 = (acc[mt][nt][2] + bj0) * oscale;
            float v3 = (acc[mt][nt][3] + bj1) * oscale;
            if (RELU) {
                v0 = fmaxf(v0, 0.0f); v1 = fmaxf(v1, 0.0f);
                v2 = fmaxf(v2, 0.0f); v3 = fmaxf(v3, 0.0f);
            }
            if (OUTH) {
                __half* Ch = (__half*)Cout;
                __half2 h0 = __floats2half2_rn(v0, v1);
                __half2 h1 = __floats2half2_rn(v2, v3);
                *(__half2*)(Ch + (size_t)r0 * M + ncol)       = h0;
                *(__half2*)(Ch + (size_t)(r0 + 8) * M + ncol) = h1;
            } else {
                float* Cf = (float*)Cout;
                *(float2*)(Cf + (size_t)r0 * M + ncol)       = make_float2(v0, v1);
                *(float2*)(Cf + (size_t)(r0 + 8) * M + ncol) = make_float2(v2, v3);
            }
        }
    }
}

template <bool RELU, bool OUTH>
__global__ void __launch_bounds__(G_THREADS) gemm_h_kernel(
    const __half* __restrict__ A, const __half* __restrict__ W,
    const float* __restrict__ bias, void* __restrict__ Cout, int K, int M)
{
    gemm_h_body<RELU, OUTH>(A, W, bias, Cout, K, M,
                            blockIdx.y * 128, blockIdx.x * 128, 1.0f);
}

#define QSCALE (0.125f * 1.4426950408889634f)   // 1/sqrt(64) * log2(e)

__global__ void __launch_bounds__(G_THREADS) qkv_h_kernel(
    const __half* __restrict__ x,
    const __half* __restrict__ wq, const float* __restrict__ bq,
    const __half* __restrict__ wk, const float* __restrict__ bk,
    const __half* __restrict__ wv, const float* __restrict__ bv,
    __half* __restrict__ q, __half* __restrict__ k, __half* __restrict__ v,
    int K, int M)
{
    const int z = blockIdx.z;
    const __half* W    = (z == 0) ? wq : (z == 1) ? wk : wv;
    const float*  bias = (z == 0) ? bq : (z == 1) ? bk : bv;
    __half*       C    = (z == 0) ? q  : (z == 1) ? k  : v;
    float oscale = (z == 0) ? QSCALE : 1.0f;
    gemm_h_body<false, true>(x, W, bias, C, K, M,
                             blockIdx.y * 128, blockIdx.x * 128, oscale);
}

// ===========================================================================
// Flash attention, fp16 mma.sync m16n8k16, base-2 online softmax (as R5).
// ===========================================================================
#define AK_PITCH 144
#define AK_BYTES (64 * AK_PITCH)
#define AP_OFF   (4 * AK_BYTES)
#define ATT_SMEM (AP_OFF + 128 * 128)

__global__ void __launch_bounds__(256, 1) attention_h_kernel(
    const __half* __restrict__ Q, const __half* __restrict__ K,
    const __half* __restrict__ V, __half* __restrict__ O)
{
    extern __shared__ char smem[];
    const uint32_t sbase = (uint32_t)__cvta_generic_to_shared(smem);

    const int tid  = threadIdx.x;
    const int lane = tid & 31;
    const int wid  = tid >> 5;
    const int b    = blockIdx.y >> 4;
    const int h    = blockIdx.y & 15;
    const int qr   = blockIdx.x * 128 + wid * 16;

    const __half* Qb = Q + ((size_t)(b * SEQ + qr)) * D_MODEL + h * HDIM;
    const __half* Kb = K + ((size_t)(b * SEQ)) * D_MODEL + h * HDIM;
    const __half* Vb = V + ((size_t)(b * SEQ)) * D_MODEL + h * HDIM;

    uint32_t qf[4][4];
    {
        const int r = lane >> 2, c2 = (lane & 3) * 2;
#pragma unroll
        for (int k16 = 0; k16 < 4; k16++) {
            qf[k16][0] = *(const uint32_t*)(Qb + (size_t)r * D_MODEL + k16 * 16 + c2);
            qf[k16][1] = *(const uint32_t*)(Qb + (size_t)(r + 8) * D_MODEL + k16 * 16 + c2);
            qf[k16][2] = *(const uint32_t*)(Qb + (size_t)r * D_MODEL + k16 * 16 + c2 + 8);
            qf[k16][3] = *(const uint32_t*)(Qb + (size_t)(r + 8) * D_MODEL + k16 * 16 + c2 + 8);
        }
    }

    auto load_kv = [&](int kt, int st) {
        const __half* Kt = Kb + (size_t)kt * 64 * D_MODEL;
        const __half* Vt = Vb + (size_t)kt * 64 * D_MODEL;
        char* kd = smem + st * AK_BYTES;
        char* vd = smem + (2 + st) * AK_BYTES;
#pragma unroll
        for (int i = 0; i < 2; i++) {
            int c = tid + 256 * i;
            int r = c >> 3, u = c & 7;
            cp_async16(kd + r * AK_PITCH + u * 16, Kt + (size_t)r * D_MODEL + u * 8);
            cp_async16(vd + r * AK_PITCH + u * 16, Vt + (size_t)r * D_MODEL + u * 8);
        }
        cp_commit();
    };

    float m0 = -1e30f, m1 = -1e30f, l0 = 0.0f, l1 = 0.0f;
    float oacc[8][4];
#pragma unroll
    for (int dt = 0; dt < 8; dt++)
#pragma unroll
        for (int r = 0; r < 4; r++) oacc[dt][r] = 0.0f;

    load_kv(0, 0);
    load_kv(1, 1);
    cp_wait1();
    __syncthreads();

    const int NKT = SEQ / 64;
    for (int kt = 0; kt < NKT; kt++) {
        const __half* kd = (const __half*)(smem + (kt & 1) * AK_BYTES);
        const uint32_t vdb = sbase + (uint32_t)((2 + (kt & 1)) * AK_BYTES);

        float sacc[8][4];
#pragma unroll
        for (int nt = 0; nt < 8; nt++) {
            sacc[nt][0] = 0.0f; sacc[nt][1] = 0.0f;
            sacc[nt][2] = 0.0f; sacc[nt][3] = 0.0f;
            const int j = nt * 8 + (lane >> 2);
#pragma unroll
            for (int k16 = 0; k16 < 4; k16++) {
                int idx = j * 72 + k16 * 16 + (lane & 3) * 2;
                uint32_t b0 = *(const uint32_t*)(kd + idx);
                uint32_t b1 = *(const uint32_t*)(kd + idx + 8);
                mma_f16(sacc[nt], qf[k16], b0, b1);
            }
        }

        float mx0 = -1e30f, mx1 = -1e30f;
#pragma unroll
        for (int nt = 0; nt < 8; nt++) {
            mx0 = fmaxf(mx0, fmaxf(sacc[nt][0], sacc[nt][1]));
            mx1 = fmaxf(mx1, fmaxf(sacc[nt][2], sacc[nt][3]));
        }
        mx0 = fmaxf(mx0, __shfl_xor_sync(0xffffffffu, mx0, 1));
        mx0 = fmaxf(mx0, __shfl_xor_sync(0xffffffffu, mx0, 2));
        mx1 = fmaxf(mx1, __shfl_xor_sync(0xffffffffu, mx1, 1));
        mx1 = fmaxf(mx1, __shfl_xor_sync(0xffffffffu, mx1, 2));
        float mn0 = fmaxf(m0, mx0), mn1 = fmaxf(m1, mx1);
        float sc0 = exp2p(m0 - mn0), sc1 = exp2p(m1 - mn1);
        m0 = mn0; m1 = mn1;

        const int prow = wid * 16 + (lane >> 2);
        char* Pb = smem + AP_OFF;
        float rs0 = 0.0f, rs1 = 0.0f;
#pragma unroll
        for (int nt = 0; nt < 8; nt++) {
            float p0 = exp2p(sacc[nt][0] - mn0);
            float p1 = exp2p(sacc[nt][1] - mn0);
            float p2 = exp2p(sacc[nt][2] - mn1);
            float p3 = exp2p(sacc[nt][3] - mn1);
            rs0 += p0 + p1;
            rs1 += p2 + p3;
            __half2 hp0 = __floats2half2_rn(p0, p1);
            __half2 hp1 = __floats2half2_rn(p2, p3);
            int bo = ((nt ^ (prow & 7)) << 4) + (lane & 3) * 4;
            *(__half2*)(Pb + prow * 128 + bo)       = hp0;
            *(__half2*)(Pb + (prow + 8) * 128 + bo) = hp1;
        }
        rs0 += __shfl_xor_sync(0xffffffffu, rs0, 1);
        rs0 += __shfl_xor_sync(0xffffffffu, rs0, 2);
        rs1 += __shfl_xor_sync(0xffffffffu, rs1, 1);
        rs1 += __shfl_xor_sync(0xffffffffu, rs1, 2);
        l0 = l0 * sc0 + rs0;
        l1 = l1 * sc1 + rs1;
#pragma unroll
        for (int dt = 0; dt < 8; dt++) {
            oacc[dt][0] *= sc0; oacc[dt][1] *= sc0;
            oacc[dt][2] *= sc1; oacc[dt][3] *= sc1;
        }
        __syncwarp();

        const uint32_t pbb = sbase + AP_OFF;
#pragma unroll
        for (int k16 = 0; k16 < 4; k16++) {
            uint32_t pf[4];
            {
                int row = wid * 16 + (lane & 7) + ((lane >> 3) & 1) * 8;
                int u   = k16 * 2 + (lane >> 4);
                LDSM_X4(pf[0], pf[1], pf[2], pf[3],
                        pbb + row * 128 + ((u ^ (row & 7)) << 4));
            }
            uint32_t vb[8][2];
#pragma unroll
            for (int ng = 0; ng < 4; ng++) {
                int j    = k16 * 16 + (lane & 7) + ((lane >> 3) & 1) * 8;
                int doff = ng * 16 + ((lane >> 4) & 1) * 8;
                LDSM_X4T(vb[ng*2][0], vb[ng*2][1], vb[ng*2+1][0], vb[ng*2+1][1],
                         vdb + j * AK_PITCH + doff * 2);
            }
#pragma unroll
            for (int dt = 0; dt < 8; dt++)
                mma_f16(oacc[dt], pf, vb[dt][0], vb[dt][1]);
        }

        __syncthreads();
        if (kt + 2 < NKT) load_kv(kt + 2, kt & 1);
        else cp_commit();
        cp_wait1();
        __syncthreads();
    }

    float inv0 = 1.0f / l0, inv1 = 1.0f / l1;
    const size_t row0 = (size_t)(b * SEQ + qr + (lane >> 2));
#pragma unroll
    for (int dt = 0; dt < 8; dt++) {
        int col = h * HDIM + dt * 8 + 2 * (lane & 3);
        __half2 h0 = __floats2half2_rn(oacc[dt][0] * inv0, oacc[dt][1] * inv0);
        __half2 h1 = __floats2half2_rn(oacc[dt][2] * inv1, oacc[dt][3] * inv1);
        *(__half2*)(O + row0 * D_MODEL + col)       = h0;
        *(__half2*)(O + (row0 + 8) * D_MODEL + col) = h1;
    }
}

// ---------------------------------------------------------------------------
// Fused residual add + LayerNorm; optional half output copy
// ---------------------------------------------------------------------------
__global__ void __launch_bounds__(256) add_ln_kernel(
    const float* __restrict__ A, const float* __restrict__ R,
    const float* __restrict__ g, const float* __restrict__ beta,
    float* __restrict__ out, __half* __restrict__ out_h)
{
    const int row = blockIdx.x;
    const int t   = threadIdx.x;

    float4 a = *(const float4*)(A + (size_t)row * D_MODEL + t * 4);
    float4 r = *(const float4*)(R + (size_t)row * D_MODEL + t * 4);
    float x0 = a.x + r.x, x1 = a.y + r.y, x2 = a.z + r.z, x3 = a.w + r.w;

    float sum = x0 + x1 + x2 + x3;
    float sq  = x0 * x0 + x1 * x1 + x2 * x2 + x3 * x3;

#pragma unroll
    for (int w = 16; w >= 1; w >>= 1) {
        sum += __shfl_xor_sync(0xffffffffu, sum, w);
        sq  += __shfl_xor_sync(0xffffffffu, sq, w);
    }
    __shared__ float ssum[8], ssq[8];
    __shared__ float s_mu, s_rstd;
    if ((t & 31) == 0) {
        ssum[t >> 5] = sum;
        ssq[t >> 5]  = sq;
    }
    __syncthreads();
    if (t == 0) {
        float S = 0.0f, Q = 0.0f;
#pragma unroll
        for (int i = 0; i < 8; i++) { S += ssum[i]; Q += ssq[i]; }
        float mu  = S * (1.0f / D_MODEL);
        float var = Q * (1.0f / D_MODEL) - mu * mu;
        s_mu   = mu;
        s_rstd = rsqrtf(var + 1e-5f);
    }
    __syncthreads();
    float mu = s_mu, rstd = s_rstd;

    float4 gg = *(const float4*)(g + t * 4);
    float4 bb = *(const float4*)(beta + t * 4);
    float4 ov;
    ov.x = (x0 - mu) * rstd * gg.x + bb.x;
    ov.y = (x1 - mu) * rstd * gg.y + bb.y;
    ov.z = (x2 - mu) * rstd * gg.z + bb.z;
    ov.w = (x3 - mu) * rstd * gg.w + bb.w;
    *(float4*)(out + (size_t)row * D_MODEL + t * 4) = ov;
    if (out_h) {
        __half2 h0 = __floats2half2_rn(ov.x, ov.y);
        __half2 h1 = __floats2half2_rn(ov.z, ov.w);
        uint2 pk;
        pk.x = *(uint32_t*)&h0;
        pk.y = *(uint32_t*)&h1;
        *(uint2*)(out_h + (size_t)row * D_MODEL + t * 4) = pk;
    }
}

// ---------------------------------------------------------------------------
extern "C" void kernel_launch(void* const* d_in, const int* in_sizes, int n_in,
                              void* d_out, int out_size)
{
    (void)in_sizes; (void)n_in; (void)out_size;

    const float* x     = (const float*)d_in[0];
    const float* w_q   = (const float*)d_in[1];
    const float* b_q   = (const float*)d_in[2];
    const float* w_k   = (const float*)d_in[3];
    const float* b_k   = (const float*)d_in[4];
    const float* w_v   = (const float*)d_in[5];
    const float* b_v   = (const float*)d_in[6];
    const float* w_o   = (const float*)d_in[7];
    const float* b_o   = (const float*)d_in[8];
    const float* w_ff1 = (const float*)d_in[9];
    const float* b_ff1 = (const float*)d_in[10];
    const float* w_ff2 = (const float*)d_in[11];
    const float* b_ff2 = (const float*)d_in[12];
    const float* ln1_g = (const float*)d_in[13];
    const float* ln1_b = (const float*)d_in[14];
    const float* ln2_g = (const float*)d_in[15];
    const float* ln2_b = (const float*)d_in[16];
    float* out = (float*)d_out;

    __half *qh, *kh, *vh, *ctxh, *hh, *ffh;
    __half *xh, *wqh, *wkh, *wvh, *woh, *ff1h, *ff2h;
    float *t1, *h;
    cudaGetSymbolAddress((void**)&qh,   g_qh);
    cudaGetSymbolAddress((void**)&kh,   g_kh);
    cudaGetSymbolAddress((void**)&vh,   g_vh);
    cudaGetSymbolAddress((void**)&ctxh, g_ctxh);
    cudaGetSymbolAddress((void**)&t1,   g_t1);
    cudaGetSymbolAddress((void**)&h,    g_h);
    cudaGetSymbolAddress((void**)&hh,   g_hh);
    cudaGetSymbolAddress((void**)&ffh,  g_ffh);
    cudaGetSymbolAddress((void**)&xh,   g_xh);
    cudaGetSymbolAddress((void**)&wqh,  g_wqh);
    cudaGetSymbolAddress((void**)&wkh,  g_wkh);
    cudaGetSymbolAddress((void**)&wvh,  g_wvh);
    cudaGetSymbolAddress((void**)&woh,  g_woh);
    cudaGetSymbolAddress((void**)&ff1h, g_ff1h);
    cudaGetSymbolAddress((void**)&ff2h, g_ff2h);

    cudaFuncSetAttribute(attention_h_kernel,
                         cudaFuncAttributeMaxDynamicSharedMemorySize, ATT_SMEM);
    cudaFuncSetAttribute(qkv_h_kernel,
                         cudaFuncAttributeMaxDynamicSharedMemorySize, G_SMEM);
    cudaFuncSetAttribute(gemm_h_kernel<false, false>,
                         cudaFuncAttributeMaxDynamicSharedMemorySize, G_SMEM);
    cudaFuncSetAttribute(gemm_h_kernel<true, true>,
                         cudaFuncAttributeMaxDynamicSharedMemorySize, G_SMEM);

    dim3 gblk(G_THREADS);

    // 1) fp32 -> fp16 prepass (single launch)
    conv_all_kernel<<<(R_TOTAL + 255) / 256, 256>>>(
        (const float4*)x, xh,
        (const float4*)w_q, wqh,
        (const float4*)w_k, wkh,
        (const float4*)w_v, wvh,
        (const float4*)w_o, woh,
        (const float4*)w_ff1, ff1h,
        (const float4*)w_ff2, ff2h);

    // 2) QKV projections (fused, grid.z = 3; q pre-scaled by QSCALE)
    qkv_h_kernel<<<dim3(D_MODEL / 128, NTOK / 128, 3), gblk, G_SMEM>>>(
        xh, wqh, b_q, wkh, b_k, wvh, b_v, qh, kh, vh, D_MODEL, D_MODEL);

    // 3) flash attention -> ctx (half)
    attention_h_kernel<<<dim3(SEQ / 128, BATCH * NHEAD), 256, ATT_SMEM>>>(
        qh, kh, vh, ctxh);

    // 4) output projection -> t1 (fp32)
    gemm_h_kernel<false, false><<<dim3(D_MODEL / 128, NTOK / 128), gblk, G_SMEM>>>(
        ctxh, woh, b_o, t1, D_MODEL, D_MODEL);

    // 5) AddNorm1 -> h (fp32) + hh (half)
    add_ln_kernel<<<NTOK, 256>>>(x, t1, ln1_g, ln1_b, h, hh);

    // 6) FFN1 (ReLU) -> ffh (half)
    gemm_h_kernel<true, true><<<dim3(D_FF / 128, NTOK / 128), gblk, G_SMEM>>>(
        hh, ff1h, b_ff1, ffh, D_MODEL, D_FF);

    // 7) FFN2 -> t1 (fp32)
    gemm_h_kernel<false, false><<<dim3(D_MODEL / 128, NTOK / 128), gblk, G_SMEM>>>(
        ffh, ff2h, b_ff2, t1, D_FF, D_MODEL);

    // 8) AddNorm2 -> output
    add_ln_kernel<<<NTOK, 256>>>(h, t1, ln2_g, ln2_b, out, nullptr);
}

// round 7
// speedup vs baseline: 6.6845x; 1.0069x over previous
#include <cuda_runtime.h>
#include <cuda_fp16.h>
#include <math.h>
#include <stdint.h>

#define D_MODEL 1024
#define D_FF    4096
#define SEQ     2048
#define BATCH   2
#define NTOK    (BATCH*SEQ)   // 4096
#define NHEAD   16
#define HDIM    64

// ---------------- scratch (device globals; no allocation allowed) ----------
__device__ __half g_qh  [NTOK * D_MODEL];
__device__ __half g_kh  [NTOK * D_MODEL];
__device__ __half g_vh  [NTOK * D_MODEL];
__device__ __half g_ctxh[NTOK * D_MODEL];
__device__ float  g_t1  [NTOK * D_MODEL];
__device__ float  g_h   [NTOK * D_MODEL];
__device__ __half g_hh  [NTOK * D_MODEL];
__device__ __half g_ffh [NTOK * D_FF];
// half copies of inputs/weights
__device__ __half g_xh  [NTOK * D_MODEL];
__device__ __half g_wqh [D_MODEL * D_MODEL];
__device__ __half g_wkh [D_MODEL * D_MODEL];
__device__ __half g_wvh [D_MODEL * D_MODEL];
__device__ __half g_woh [D_MODEL * D_MODEL];
__device__ __half g_ff1h[D_MODEL * D_FF];
__device__ __half g_ff2h[D_FF * D_MODEL];

// ---------------------------------------------------------------------------
__device__ __forceinline__ void cp_async16(void* smem_dst, const void* gmem_src) {
    uint32_t da = (uint32_t)__cvta_generic_to_shared(smem_dst);
    asm volatile("cp.async.cg.shared.global [%0], [%1], 16;\n" :: "r"(da), "l"(gmem_src));
}
__device__ __forceinline__ void cp_commit() {
    asm volatile("cp.async.commit_group;\n");
}
__device__ __forceinline__ void cp_wait1() {
    asm volatile("cp.async.wait_group 1;\n");
}
__device__ __forceinline__ void mma_f16(float* c, const uint32_t* a,
                                        uint32_t b0, uint32_t b1) {
    asm volatile(
        "mma.sync.aligned.m16n8k16.row.col.f32.f16.f16.f32 "
        "{%0,%1,%2,%3}, {%4,%5,%6,%7}, {%8,%9}, {%0,%1,%2,%3};"
        : "+f"(c[0]), "+f"(c[1]), "+f"(c[2]), "+f"(c[3])
        : "r"(a[0]), "r"(a[1]), "r"(a[2]), "r"(a[3]), "r"(b0), "r"(b1));
}
#define LDSM_X4(r0, r1, r2, r3, addr) \
    asm volatile("ldmatrix.sync.aligned.m8n8.x4.shared.b16 {%0,%1,%2,%3}, [%4];" \
        : "=r"(r0), "=r"(r1), "=r"(r2), "=r"(r3) : "r"(addr))
#define LDSM_X4T(r0, r1, r2, r3, addr) \
    asm volatile("ldmatrix.sync.aligned.m8n8.x4.trans.shared.b16 {%0,%1,%2,%3}, [%4];" \
        : "=r"(r0), "=r"(r1), "=r"(r2), "=r"(r3) : "r"(addr))

// fast exp2 on the FMA pipe (x <= 0), rel err ~2e-6
__device__ __forceinline__ float exp2p(float x) {
    x = fmaxf(x, -126.0f);
    float z = x + 12582912.0f;
    float f = x - (z - 12582912.0f);
    float p =            1.3333558146e-3f;
    p = fmaf(p, f, 9.6181291918e-3f);
    p = fmaf(p, f, 5.5504108664e-2f);
    p = fmaf(p, f, 2.4022650695e-1f);
    p = fmaf(p, f, 6.9314718056e-1f);
    p = fmaf(p, f, 1.0f);
    return __int_as_float((__float_as_int(z) << 23) + __float_as_int(p));
}

// ===========================================================================
// Prepass: convert x + 6 weight tensors fp32 -> fp16 in ONE launch.
// ===========================================================================
#define R_N0 (NTOK * D_MODEL / 4)
#define R_N1 (D_MODEL * D_MODEL / 4)
#define R_N2 (D_MODEL * D_FF / 4)
#define R_TOTAL (R_N0 + 4 * R_N1 + 2 * R_N2)

__global__ void __launch_bounds__(256) conv_all_kernel(
    const float4* __restrict__ x,   __half* __restrict__ xh,
    const float4* __restrict__ wq,  __half* __restrict__ wqh,
    const float4* __restrict__ wk,  __half* __restrict__ wkh,
    const float4* __restrict__ wv,  __half* __restrict__ wvh,
    const float4* __restrict__ wo,  __half* __restrict__ woh,
    const float4* __restrict__ f1,  __half* __restrict__ f1h,
    const float4* __restrict__ f2,  __half* __restrict__ f2h)
{
    int i = blockIdx.x * 256 + threadIdx.x;
    if (i >= R_TOTAL) return;
    const float4* s; __half* d; int off;
    if      (i < R_N0)                 { s = x;  d = xh;  off = 0; }
    else if (i < R_N0 + R_N1)          { s = wq; d = wqh; off = R_N0; }
    else if (i < R_N0 + 2*R_N1)        { s = wk; d = wkh; off = R_N0 + R_N1; }
    else if (i < R_N0 + 3*R_N1)        { s = wv; d = wvh; off = R_N0 + 2*R_N1; }
    else if (i < R_N0 + 4*R_N1)        { s = wo; d = woh; off = R_N0 + 3*R_N1; }
    else if (i < R_N0 + 4*R_N1 + R_N2) { s = f1; d = f1h; off = R_N0 + 4*R_N1; }
    else                               { s = f2; d = f2h; off = R_N0 + 4*R_N1 + R_N2; }
    int j = i - off;
    float4 v = s[j];
    __half2 h0 = __floats2half2_rn(v.x, v.y);
    __half2 h1 = __floats2half2_rn(v.z, v.w);
    uint2 pk;
    pk.x = *(uint32_t*)&h0;
    pk.y = *(uint32_t*)&h1;
    *(uint2*)(d + (size_t)j * 4) = pk;
}

// ===========================================================================
// fp16 tensor-core GEMM: C[N,M] = A[N,K] @ W[K,M] + bias (+ReLU)(*oscale)
// CTA 128x128, BK=64, 3-stage cp.async, 4 warps (2x2), warp tile 64x64.
// Register-level double-buffered fragments: LDSMs of k16+1 overlap the 32
// HMMAs of k16, hiding ldmatrix latency inside the tile.
// ===========================================================================
#define GA_BYTES 16384              // 128 rows * 128B
#define GB_PITCH 272                // 128 halves + 8 pad, bytes
#define GB_BYTES (64 * GB_PITCH)    // 17408
#define G_STAGE  (GA_BYTES + GB_BYTES)
#define G_SMEM   (3 * G_STAGE)      // 101376
#define G_THREADS 128

template <bool RELU, bool OUTH>
__device__ __forceinline__ void gemm_h_body(
    const __half* __restrict__ A, const __half* __restrict__ W,
    const float* __restrict__ bias, void* __restrict__ Cout,
    int K, int M, int row0, int col0, float oscale)
{
    extern __shared__ char smem[];
    const int tid  = threadIdx.x;
    const int lane = tid & 31;
    const int wid  = tid >> 5;
    const int warp_m = wid & 1;   // 2 x 64 rows
    const int warp_n = wid >> 1;  // 2 x 64 cols
    const uint32_t sbase = (uint32_t)__cvta_generic_to_shared(smem);

    float acc[4][8][4];
#pragma unroll
    for (int mt = 0; mt < 4; mt++)
#pragma unroll
        for (int nt = 0; nt < 8; nt++)
#pragma unroll
            for (int r = 0; r < 4; r++) acc[mt][nt][r] = 0.0f;

    const int KT = K / 64;

    auto load_stage = [&](int kt) {
        char* base = smem + (kt % 3) * G_STAGE;
        const int k0 = kt * 64;
#pragma unroll
        for (int i = 0; i < 8; i++) {           // A: 1024 x 16B
            int c = tid + G_THREADS * i;
            int r = c >> 3, u = c & 7;
            cp_async16(base + r * 128 + (((u ^ (r & 7))) << 4),
                       A + (size_t)(row0 + r) * K + k0 + u * 8);
        }
#pragma unroll
        for (int i = 0; i < 8; i++) {           // B: 1024 x 16B
            int c = tid + G_THREADS * i;
            int k = c >> 4, u = c & 15;
            cp_async16(base + GA_BYTES + k * GB_PITCH + u * 16,
                       W + (size_t)(k0 + k) * M + col0 + u * 8);
        }
        cp_commit();
    };

    load_stage(0);
    load_stage(1);

    // double-buffered register fragments
    uint32_t af[2][4][4];
    uint32_t bf[2][8][2];

    for (int kt = 0; kt < KT; kt++) {
        cp_wait1();
        __syncthreads();
        if (kt + 2 < KT) load_stage(kt + 2);
        else cp_commit();

        const uint32_t ab = sbase + (uint32_t)((kt % 3) * G_STAGE);
        const uint32_t bb = ab + GA_BYTES;

        auto ld_frags = [&](int k16, int buf) {
#pragma unroll
            for (int mt = 0; mt < 4; mt++) {
                int m = warp_m * 64 + mt * 16 + (lane & 7) + ((lane >> 3) & 1) * 8;
                int u = k16 * 2 + (lane >> 4);
                LDSM_X4(af[buf][mt][0], af[buf][mt][1], af[buf][mt][2], af[buf][mt][3],
                        ab + m * 128 + ((u ^ (m & 7)) << 4));
            }
#pragma unroll
            for (int ng = 0; ng < 4; ng++) {
                int k    = k16 * 16 + (lane & 7) + ((lane >> 3) & 1) * 8;
                int noff = warp_n * 64 + ng * 16 + ((lane >> 4) & 1) * 8;
                LDSM_X4T(bf[buf][ng*2][0], bf[buf][ng*2][1],
                         bf[buf][ng*2+1][0], bf[buf][ng*2+1][1],
                         bb + k * GB_PITCH + noff * 2);
            }
        };

        ld_frags(0, 0);
#pragma unroll
        for (int k16 = 0; k16 < 4; k16++) {
            const int cur = k16 & 1;
            if (k16 < 3) ld_frags(k16 + 1, cur ^ 1);
#pragma unroll
            for (int mt = 0; mt < 4; mt++)
#pragma unroll
                for (int nt = 0; nt < 8; nt++)
                    mma_f16(acc[mt][nt], af[cur][mt], bf[cur][nt][0], bf[cur][nt][1]);
        }
        // NOTE: no trailing __syncthreads — the post-wait barrier of the next
        // iteration orders stage reuse (loads for stage s are issued only
        // after every warp has passed that barrier, i.e. finished reading s).
    }

    // ---- epilogue ----
#pragma unroll
    for (int nt = 0; nt < 8; nt++) {
        int ncol = col0 + warp_n * 64 + nt * 8 + (lane & 3) * 2;
        float bj0 = bias[ncol];
        float bj1 = bias[ncol + 1];
#pragma unroll
        for (int mt = 0; mt < 4; mt++) {
            int r0 = row0 + warp_m * 64 + mt * 16 + (lane >> 2);
            float v0 = (acc[mt][nt][0] + bj0) * oscale;
            float v1 = (acc[mt][nt][1] + bj1) * oscale;
            float v2 = (acc[mt][nt][2] + bj0) * oscale;
            float v3 = (acc[mt][nt][3] + bj1) * oscale;
            if (RELU) {
                v0 = fmaxf(v0, 0.0f); v1 = fmaxf(v1, 0.0f);
                v2 = fmaxf(v2, 0.0f); v3 = fmaxf(v3, 0.0f);
            }
            if (OUTH) {
                __half* Ch = (__half*)Cout;
                __half2 h0 = __floats2half2_rn(v0, v1);
                __half2 h1 = __floats2half2_rn(v2, v3);
                *(__half2*)(Ch + (size_t)r0 * M + ncol)       = h0;
                *(__half2*)(Ch + (size_t)(r0 + 8) * M + ncol) = h1;
            } else {
                float* Cf = (float*)Cout;
                *(float2*)(Cf + (size_t)r0 * M + ncol)       = make_float2(v0, v1);
                *(float2*)(Cf + (size_t)(r0 + 8) * M + ncol) = make_float2(v2, v3);
            }
        }
    }
}

template <bool RELU, bool OUTH>
__global__ void __launch_bounds__(G_THREADS) gemm_h_kernel(
    const __half* __restrict__ A, const __half* __restrict__ W,
    const float* __restrict__ bias, void* __restrict__ Cout, int K, int M)
{
    gemm_h_body<RELU, OUTH>(A, W, bias, Cout, K, M,
                            blockIdx.y * 128, blockIdx.x * 128, 1.0f);
}

#define QSCALE (0.125f * 1.4426950408889634f)   // 1/sqrt(64) * log2(e)

__global__ void __launch_bounds__(G_THREADS) qkv_h_kernel(
    const __half* __restrict__ x,
    const __half* __restrict__ wq, const float* __restrict__ bq,
    const __half* __restrict__ wk, const float* __restrict__ bk,
    const __half* __restrict__ wv, const float* __restrict__ bv,
    __half* __restrict__ q, __half* __restrict__ k, __half* __restrict__ v,
    int K, int M)
{
    const int z = blockIdx.z;
    const __half* W    = (z == 0) ? wq : (z == 1) ? wk : wv;
    const float*  bias = (z == 0) ? bq : (z == 1) ? bk : bv;
    __half*       C    = (z == 0) ? q  : (z == 1) ? k  : v;
    float oscale = (z == 0) ? QSCALE : 1.0f;
    gemm_h_body<false, true>(x, W, bias, C, K, M,
                             blockIdx.y * 128, blockIdx.x * 128, oscale);
}

// ===========================================================================
// Flash attention, fp16 mma.sync m16n8k16, base-2 online softmax (as R5/R6).
// ===========================================================================
#define AK_PITCH 144
#define AK_BYTES (64 * AK_PITCH)
#define AP_OFF   (4 * AK_BYTES)
#define ATT_SMEM (AP_OFF + 128 * 128)

__global__ void __launch_bounds__(256, 1) attention_h_kernel(
    const __half* __restrict__ Q, const __half* __restrict__ K,
    const __half* __restrict__ V, __half* __restrict__ O)
{
    extern __shared__ char smem[];
    const uint32_t sbase = (uint32_t)__cvta_generic_to_shared(smem);

    const int tid  = threadIdx.x;
    const int lane = tid & 31;
    const int wid  = tid >> 5;
    const int b    = blockIdx.y >> 4;
    const int h    = blockIdx.y & 15;
    const int qr   = blockIdx.x * 128 + wid * 16;

    const __half* Qb = Q + ((size_t)(b * SEQ + qr)) * D_MODEL + h * HDIM;
    const __half* Kb = K + ((size_t)(b * SEQ)) * D_MODEL + h * HDIM;
    const __half* Vb = V + ((size_t)(b * SEQ)) * D_MODEL + h * HDIM;

    uint32_t qf[4][4];
    {
        const int r = lane >> 2, c2 = (lane & 3) * 2;
#pragma unroll
        for (int k16 = 0; k16 < 4; k16++) {
            qf[k16][0] = *(const uint32_t*)(Qb + (size_t)r * D_MODEL + k16 * 16 + c2);
            qf[k16][1] = *(const uint32_t*)(Qb + (size_t)(r + 8) * D_MODEL + k16 * 16 + c2);
            qf[k16][2] = *(const uint32_t*)(Qb + (size_t)r * D_MODEL + k16 * 16 + c2 + 8);
            qf[k16][3] = *(const uint32_t*)(Qb + (size_t)(r + 8) * D_MODEL + k16 * 16 + c2 + 8);
        }
    }

    auto load_kv = [&](int kt, int st) {
        const __half* Kt = Kb + (size_t)kt * 64 * D_MODEL;
        const __half* Vt = Vb + (size_t)kt * 64 * D_MODEL;
        char* kd = smem + st * AK_BYTES;
        char* vd = smem + (2 + st) * AK_BYTES;
#pragma unroll
        for (int i = 0; i < 2; i++) {
            int c = tid + 256 * i;
            int r = c >> 3, u = c & 7;
            cp_async16(kd + r * AK_PITCH + u * 16, Kt + (size_t)r * D_MODEL + u * 8);
            cp_async16(vd + r * AK_PITCH + u * 16, Vt + (size_t)r * D_MODEL + u * 8);
        }
        cp_commit();
    };

    float m0 = -1e30f, m1 = -1e30f, l0 = 0.0f, l1 = 0.0f;
    float oacc[8][4];
#pragma unroll
    for (int dt = 0; dt < 8; dt++)
#pragma unroll
        for (int r = 0; r < 4; r++) oacc[dt][r] = 0.0f;

    load_kv(0, 0);
    load_kv(1, 1);
    cp_wait1();
    __syncthreads();

    const int NKT = SEQ / 64;
    for (int kt = 0; kt < NKT; kt++) {
        const __half* kd = (const __half*)(smem + (kt & 1) * AK_BYTES);
        const uint32_t vdb = sbase + (uint32_t)((2 + (kt & 1)) * AK_BYTES);

        float sacc[8][4];
#pragma unroll
        for (int nt = 0; nt < 8; nt++) {
            sacc[nt][0] = 0.0f; sacc[nt][1] = 0.0f;
            sacc[nt][2] = 0.0f; sacc[nt][3] = 0.0f;
            const int j = nt * 8 + (lane >> 2);
#pragma unroll
            for (int k16 = 0; k16 < 4; k16++) {
                int idx = j * 72 + k16 * 16 + (lane & 3) * 2;
                uint32_t b0 = *(const uint32_t*)(kd + idx);
                uint32_t b1 = *(const uint32_t*)(kd + idx + 8);
                mma_f16(sacc[nt], qf[k16], b0, b1);
            }
        }

        float mx0 = -1e30f, mx1 = -1e30f;
#pragma unroll
        for (int nt = 0; nt < 8; nt++) {
            mx0 = fmaxf(mx0, fmaxf(sacc[nt][0], sacc[nt][1]));
            mx1 = fmaxf(mx1, fmaxf(sacc[nt][2], sacc[nt][3]));
        }
        mx0 = fmaxf(mx0, __shfl_xor_sync(0xffffffffu, mx0, 1));
        mx0 = fmaxf(mx0, __shfl_xor_sync(0xffffffffu, mx0, 2));
        mx1 = fmaxf(mx1, __shfl_xor_sync(0xffffffffu, mx1, 1));
        mx1 = fmaxf(mx1, __shfl_xor_sync(0xffffffffu, mx1, 2));
        float mn0 = fmaxf(m0, mx0), mn1 = fmaxf(m1, mx1);
        float sc0 = exp2p(m0 - mn0), sc1 = exp2p(m1 - mn1);
        m0 = mn0; m1 = mn1;

        const int prow = wid * 16 + (lane >> 2);
        char* Pb = smem + AP_OFF;
        float rs0 = 0.0f, rs1 = 0.0f;
#pragma unroll
        for (int nt = 0; nt < 8; nt++) {
            float p0 = exp2p(sacc[nt][0] - mn0);
            float p1 = exp2p(sacc[nt][1] - mn0);
            float p2 = exp2p(sacc[nt][2] - mn1);
            float p3 = exp2p(sacc[nt][3] - mn1);
            rs0 += p0 + p1;
            rs1 += p2 + p3;
            __half2 hp0 = __floats2half2_rn(p0, p1);
            __half2 hp1 = __floats2half2_rn(p2, p3);
            int bo = ((nt ^ (prow & 7)) << 4) + (lane & 3) * 4;
            *(__half2*)(Pb + prow * 128 + bo)       = hp0;
            *(__half2*)(Pb + (prow + 8) * 128 + bo) = hp1;
        }
        rs0 += __shfl_xor_sync(0xffffffffu, rs0, 1);
        rs0 += __shfl_xor_sync(0xffffffffu, rs0, 2);
        rs1 += __shfl_xor_sync(0xffffffffu, rs1, 1);
        rs1 += __shfl_xor_sync(0xffffffffu, rs1, 2);
        l0 = l0 * sc0 + rs0;
        l1 = l1 * sc1 + rs1;
#pragma unroll
        for (int dt = 0; dt < 8; dt++) {
            oacc[dt][0] *= sc0; oacc[dt][1] *= sc0;
            oacc[dt][2] *= sc1; oacc[dt][3] *= sc1;
        }
        __syncwarp();

        const uint32_t pbb = sbase + AP_OFF;
#pragma unroll
        for (int k16 = 0; k16 < 4; k16++) {
            uint32_t pf[4];
            {
                int row = wid * 16 + (lane & 7) + ((lane >> 3) & 1) * 8;
                int u   = k16 * 2 + (lane >> 4);
                LDSM_X4(pf[0], pf[1], pf[2], pf[3],
                        pbb + row * 128 + ((u ^ (row & 7)) << 4));
            }
            uint32_t vb[8][2];
#pragma unroll
            for (int ng = 0; ng < 4; ng++) {
                int j    = k16 * 16 + (lane & 7) + ((lane >> 3) & 1) * 8;
                int doff = ng * 16 + ((lane >> 4) & 1) * 8;
                LDSM_X4T(vb[ng*2][0], vb[ng*2][1], vb[ng*2+1][0], vb[ng*2+1][1],
                         vdb + j * AK_PITCH + doff * 2);
            }
#pragma unroll
            for (int dt = 0; dt < 8; dt++)
                mma_f16(oacc[dt], pf, vb[dt][0], vb[dt][1]);
        }

        __syncthreads();
        if (kt + 2 < NKT) load_kv(kt + 2, kt & 1);
        else cp_commit();
        cp_wait1();
        __syncthreads();
    }

    float inv0 = 1.0f / l0, inv1 = 1.0f / l1;
    const size_t row0 = (size_t)(b * SEQ + qr + (lane >> 2));
#pragma unroll
    for (int dt = 0; dt < 8; dt++) {
        int col = h * HDIM + dt * 8 + 2 * (lane & 3);
        __half2 h0 = __floats2half2_rn(oacc[dt][0] * inv0, oacc[dt][1] * inv0);
        __half2 h1 = __floats2half2_rn(oacc[dt][2] * inv1, oacc[dt][3] * inv1);
        *(__half2*)(O + row0 * D_MODEL + col)       = h0;
        *(__half2*)(O + (row0 + 8) * D_MODEL + col) = h1;
    }
}

// ---------------------------------------------------------------------------
// Fused residual add + LayerNorm; optional half output copy
// ---------------------------------------------------------------------------
__global__ void __launch_bounds__(256) add_ln_kernel(
    const float* __restrict__ A, const float* __restrict__ R,
    const float* __restrict__ g, const float* __restrict__ beta,
    float* __restrict__ out, __half* __restrict__ out_h)
{
    const int row = blockIdx.x;
    const int t   = threadIdx.x;

    float4 a = *(const float4*)(A + (size_t)row * D_MODEL + t * 4);
    float4 r = *(const float4*)(R + (size_t)row * D_MODEL + t * 4);
    float x0 = a.x + r.x, x1 = a.y + r.y, x2 = a.z + r.z, x3 = a.w + r.w;

    float sum = x0 + x1 + x2 + x3;
    float sq  = x0 * x0 + x1 * x1 + x2 * x2 + x3 * x3;

#pragma unroll
    for (int w = 16; w >= 1; w >>= 1) {
        sum += __shfl_xor_sync(0xffffffffu, sum, w);
        sq  += __shfl_xor_sync(0xffffffffu, sq, w);
    }
    __shared__ float ssum[8], ssq[8];
    __shared__ float s_mu, s_rstd;
    if ((t & 31) == 0) {
        ssum[t >> 5] = sum;
        ssq[t >> 5]  = sq;
    }
    __syncthreads();
    if (t == 0) {
        float S = 0.0f, Q = 0.0f;
#pragma unroll
        for (int i = 0; i < 8; i++) { S += ssum[i]; Q += ssq[i]; }
        float mu  = S * (1.0f / D_MODEL);
        float var = Q * (1.0f / D_MODEL) - mu * mu;
        s_mu   = mu;
        s_rstd = rsqrtf(var + 1e-5f);
    }
    __syncthreads();
    float mu = s_mu, rstd = s_rstd;

    float4 gg = *(const float4*)(g + t * 4);
    float4 bb = *(const float4*)(beta + t * 4);
    float4 ov;
    ov.x = (x0 - mu) * rstd * gg.x + bb.x;
    ov.y = (x1 - mu) * rstd * gg.y + bb.y;
    ov.z = (x2 - mu) * rstd * gg.z + bb.z;
    ov.w = (x3 - mu) * rstd * gg.w + bb.w;
    *(float4*)(out + (size_t)row * D_MODEL + t * 4) = ov;
    if (out_h) {
        __half2 h0 = __floats2half2_rn(ov.x, ov.y);
        __half2 h1 = __floats2half2_rn(ov.z, ov.w);
        uint2 pk;
        pk.x = *(uint32_t*)&h0;
        pk.y = *(uint32_t*)&h1;
        *(uint2*)(out_h + (size_t)row * D_MODEL + t * 4) = pk;
    }
}

// ---------------------------------------------------------------------------
extern "C" void kernel_launch(void* const* d_in, const int* in_sizes, int n_in,
                              void* d_out, int out_size)
{
    (void)in_sizes; (void)n_in; (void)out_size;

    const float* x     = (const float*)d_in[0];
    const float* w_q   = (const float*)d_in[1];
    const float* b_q   = (const float*)d_in[2];
    const float* w_k   = (const float*)d_in[3];
    const float* b_k   = (const float*)d_in[4];
    const float* w_v   = (const float*)d_in[5];
    const float* b_v   = (const float*)d_in[6];
    const float* w_o   = (const float*)d_in[7];
    const float* b_o   = (const float*)d_in[8];
    const float* w_ff1 = (const float*)d_in[9];
    const float* b_ff1 = (const float*)d_in[10];
    const float* w_ff2 = (const float*)d_in[11];
    const float* b_ff2 = (const float*)d_in[12];
    const float* ln1_g = (const float*)d_in[13];
    const float* ln1_b = (const float*)d_in[14];
    const float* ln2_g = (const float*)d_in[15];
    const float* ln2_b = (const float*)d_in[16];
    float* out = (float*)d_out;

    __half *qh, *kh, *vh, *ctxh, *hh, *ffh;
    __half *xh, *wqh, *wkh, *wvh, *woh, *ff1h, *ff2h;
    float *t1, *h;
    cudaGetSymbolAddress((void**)&qh,   g_qh);
    cudaGetSymbolAddress((void**)&kh,   g_kh);
    cudaGetSymbolAddress((void**)&vh,   g_vh);
    cudaGetSymbolAddress((void**)&ctxh, g_ctxh);
    cudaGetSymbolAddress((void**)&t1,   g_t1);
    cudaGetSymbolAddress((void**)&h,    g_h);
    cudaGetSymbolAddress((void**)&hh,   g_hh);
    cudaGetSymbolAddress((void**)&ffh,  g_ffh);
    cudaGetSymbolAddress((void**)&xh,   g_xh);
    cudaGetSymbolAddress((void**)&wqh,  g_wqh);
    cudaGetSymbolAddress((void**)&wkh,  g_wkh);
    cudaGetSymbolAddress((void**)&wvh,  g_wvh);
    cudaGetSymbolAddress((void**)&woh,  g_woh);
    cudaGetSymbolAddress((void**)&ff1h, g_ff1h);
    cudaGetSymbolAddress((void**)&ff2h, g_ff2h);

    cudaFuncSetAttribute(attention_h_kernel,
                         cudaFuncAttributeMaxDynamicSharedMemorySize, ATT_SMEM);
    cudaFuncSetAttribute(qkv_h_kernel,
                         cudaFuncAttributeMaxDynamicSharedMemorySize, G_SMEM);
    cudaFuncSetAttribute(gemm_h_kernel<false, false>,
                         cudaFuncAttributeMaxDynamicSharedMemorySize, G_SMEM);
    cudaFuncSetAttribute(gemm_h_kernel<true, true>,
                         cudaFuncAttributeMaxDynamicSharedMemorySize, G_SMEM);

    dim3 gblk(G_THREADS);

    // 1) fp32 -> fp16 prepass (single launch)
    conv_all_kernel<<<(R_TOTAL + 255) / 256, 256>>>(
        (const float4*)x, xh,
        (const float4*)w_q, wqh,
        (const float4*)w_k, wkh,
        (const float4*)w_v, wvh,
        (const float4*)w_o, woh,
        (const float4*)w_ff1, ff1h,
        (const float4*)w_ff2, ff2h);

    // 2) QKV projections (fused, grid.z = 3; q pre-scaled by QSCALE)
    qkv_h_kernel<<<dim3(D_MODEL / 128, NTOK / 128, 3), gblk, G_SMEM>>>(
        xh, wqh, b_q, wkh, b_k, wvh, b_v, qh, kh, vh, D_MODEL, D_MODEL);

    // 3) flash attention -> ctx (half)
    attention_h_kernel<<<dim3(SEQ / 128, BATCH * NHEAD), 256, ATT_SMEM>>>(
        qh, kh, vh, ctxh);

    // 4) output projection -> t1 (fp32)
    gemm_h_kernel<false, false><<<dim3(D_MODEL / 128, NTOK / 128), gblk, G_SMEM>>>(
        ctxh, woh, b_o, t1, D_MODEL, D_MODEL);

    // 5) AddNorm1 -> h (fp32) + hh (half)
    add_ln_kernel<<<NTOK, 256>>>(x, t1, ln1_g, ln1_b, h, hh);

    // 6) FFN1 (ReLU) -> ffh (half)
    gemm_h_kernel<true, true><<<dim3(D_FF / 128, NTOK / 128), gblk, G_SMEM>>>(
        hh, ff1h, b_ff1, ffh, D_MODEL, D_FF);

    // 7) FFN2 -> t1 (fp32)
    gemm_h_kernel<false, false><<<dim3(D_MODEL / 128, NTOK / 128), gblk, G_SMEM>>>(
        ffh, ff2h, b_ff2, t1, D_FF, D_MODEL);

    // 8) AddNorm2 -> output
    add_ln_kernel<<<NTOK, 256>>>(h, t1, ln2_g, ln2_b, out, nullptr);
}

// round 8
// speedup vs baseline: 6.8167x; 1.0198x over previous
#include <cuda_runtime.h>
#include <cuda_fp16.h>
#include <math.h>
#include <stdint.h>

#define D_MODEL 1024
#define D_FF    4096
#define SEQ     2048
#define BATCH   2
#define NTOK    (BATCH*SEQ)   // 4096
#define NHEAD   16
#define HDIM    64

// ---------------- scratch (device globals; no allocation allowed) ----------
__device__ __half g_qh  [NTOK * D_MODEL];
__device__ __half g_kh  [NTOK * D_MODEL];
__device__ __half g_vh  [NTOK * D_MODEL];
__device__ __half g_ctxh[NTOK * D_MODEL];
__device__ float  g_t1  [NTOK * D_MODEL];
__device__ float  g_h   [NTOK * D_MODEL];
__device__ __half g_hh  [NTOK * D_MODEL];
__device__ __half g_ffh [NTOK * D_FF];
// half copies of inputs/weights
__device__ __half g_xh  [NTOK * D_MODEL];
__device__ __half g_wqh [D_MODEL * D_MODEL];
__device__ __half g_wkh [D_MODEL * D_MODEL];
__device__ __half g_wvh [D_MODEL * D_MODEL];
__device__ __half g_woh [D_MODEL * D_MODEL];
__device__ __half g_ff1h[D_MODEL * D_FF];
__device__ __half g_ff2h[D_FF * D_MODEL];

// ---------------------------------------------------------------------------
__device__ __forceinline__ void cp_async16(void* smem_dst, const void* gmem_src) {
    uint32_t da = (uint32_t)__cvta_generic_to_shared(smem_dst);
    asm volatile("cp.async.cg.shared.global [%0], [%1], 16;\n" :: "r"(da), "l"(gmem_src));
}
__device__ __forceinline__ void cp_commit() {
    asm volatile("cp.async.commit_group;\n");
}
__device__ __forceinline__ void cp_wait1() {
    asm volatile("cp.async.wait_group 1;\n");
}
__device__ __forceinline__ void mma_f16(float* c, const uint32_t* a,
                                        uint32_t b0, uint32_t b1) {
    asm volatile(
        "mma.sync.aligned.m16n8k16.row.col.f32.f16.f16.f32 "
        "{%0,%1,%2,%3}, {%4,%5,%6,%7}, {%8,%9}, {%0,%1,%2,%3};"
        : "+f"(c[0]), "+f"(c[1]), "+f"(c[2]), "+f"(c[3])
        : "r"(a[0]), "r"(a[1]), "r"(a[2]), "r"(a[3]), "r"(b0), "r"(b1));
}
#define LDSM_X4(r0, r1, r2, r3, addr) \
    asm volatile("ldmatrix.sync.aligned.m8n8.x4.shared.b16 {%0,%1,%2,%3}, [%4];" \
        : "=r"(r0), "=r"(r1), "=r"(r2), "=r"(r3) : "r"(addr))
#define LDSM_X4T(r0, r1, r2, r3, addr) \
    asm volatile("ldmatrix.sync.aligned.m8n8.x4.trans.shared.b16 {%0,%1,%2,%3}, [%4];" \
        : "=r"(r0), "=r"(r1), "=r"(r2), "=r"(r3) : "r"(addr))

// fast exp2 on the FMA pipe (x <= 0), rel err ~2e-6
__device__ __forceinline__ float exp2p(float x) {
    x = fmaxf(x, -126.0f);
    float z = x + 12582912.0f;
    float f = x - (z - 12582912.0f);
    float p =            1.3333558146e-3f;
    p = fmaf(p, f, 9.6181291918e-3f);
    p = fmaf(p, f, 5.5504108664e-2f);
    p = fmaf(p, f, 2.4022650695e-1f);
    p = fmaf(p, f, 6.9314718056e-1f);
    p = fmaf(p, f, 1.0f);
    return __int_as_float((__float_as_int(z) << 23) + __float_as_int(p));
}

// ===========================================================================
// Prepass: convert x + 6 weight tensors fp32 -> fp16 in ONE launch.
// ===========================================================================
#define R_N0 (NTOK * D_MODEL / 4)
#define R_N1 (D_MODEL * D_MODEL / 4)
#define R_N2 (D_MODEL * D_FF / 4)
#define R_TOTAL (R_N0 + 4 * R_N1 + 2 * R_N2)

__global__ void __launch_bounds__(256) conv_all_kernel(
    const float4* __restrict__ x,   __half* __restrict__ xh,
    const float4* __restrict__ wq,  __half* __restrict__ wqh,
    const float4* __restrict__ wk,  __half* __restrict__ wkh,
    const float4* __restrict__ wv,  __half* __restrict__ wvh,
    const float4* __restrict__ wo,  __half* __restrict__ woh,
    const float4* __restrict__ f1,  __half* __restrict__ f1h,
    const float4* __restrict__ f2,  __half* __restrict__ f2h)
{
    int i = blockIdx.x * 256 + threadIdx.x;
    if (i >= R_TOTAL) return;
    const float4* s; __half* d; int off;
    if      (i < R_N0)                 { s = x;  d = xh;  off = 0; }
    else if (i < R_N0 + R_N1)          { s = wq; d = wqh; off = R_N0; }
    else if (i < R_N0 + 2*R_N1)        { s = wk; d = wkh; off = R_N0 + R_N1; }
    else if (i < R_N0 + 3*R_N1)        { s = wv; d = wvh; off = R_N0 + 2*R_N1; }
    else if (i < R_N0 + 4*R_N1)        { s = wo; d = woh; off = R_N0 + 3*R_N1; }
    else if (i < R_N0 + 4*R_N1 + R_N2) { s = f1; d = f1h; off = R_N0 + 4*R_N1; }
    else                               { s = f2; d = f2h; off = R_N0 + 4*R_N1 + R_N2; }
    int j = i - off;
    float4 v = s[j];
    __half2 h0 = __floats2half2_rn(v.x, v.y);
    __half2 h1 = __floats2half2_rn(v.z, v.w);
    uint2 pk;
    pk.x = *(uint32_t*)&h0;
    pk.y = *(uint32_t*)&h1;
    *(uint2*)(d + (size_t)j * 4) = pk;
}

// ===========================================================================
// fp16 tensor-core GEMM (R7 config — at the mma.sync plateau; unchanged).
// CTA 128x128, BK=64, 3-stage cp.async, 4 warps (2x2), warp tile 64x64.
// ===========================================================================
#define GA_BYTES 16384
#define GB_PITCH 272
#define GB_BYTES (64 * GB_PITCH)
#define G_STAGE  (GA_BYTES + GB_BYTES)
#define G_SMEM   (3 * G_STAGE)
#define G_THREADS 128

template <bool RELU, bool OUTH>
__device__ __forceinline__ void gemm_h_body(
    const __half* __restrict__ A, const __half* __restrict__ W,
    const float* __restrict__ bias, void* __restrict__ Cout,
    int K, int M, int row0, int col0, float oscale)
{
    extern __shared__ char smem[];
    const int tid  = threadIdx.x;
    const int lane = tid & 31;
    const int wid  = tid >> 5;
    const int warp_m = wid & 1;
    const int warp_n = wid >> 1;
    const uint32_t sbase = (uint32_t)__cvta_generic_to_shared(smem);

    float acc[4][8][4];
#pragma unroll
    for (int mt = 0; mt < 4; mt++)
#pragma unroll
        for (int nt = 0; nt < 8; nt++)
#pragma unroll
            for (int r = 0; r < 4; r++) acc[mt][nt][r] = 0.0f;

    const int KT = K / 64;

    auto load_stage = [&](int kt) {
        char* base = smem + (kt % 3) * G_STAGE;
        const int k0 = kt * 64;
#pragma unroll
        for (int i = 0; i < 8; i++) {
            int c = tid + G_THREADS * i;
            int r = c >> 3, u = c & 7;
            cp_async16(base + r * 128 + (((u ^ (r & 7))) << 4),
                       A + (size_t)(row0 + r) * K + k0 + u * 8);
        }
#pragma unroll
        for (int i = 0; i < 8; i++) {
            int c = tid + G_THREADS * i;
            int k = c >> 4, u = c & 15;
            cp_async16(base + GA_BYTES + k * GB_PITCH + u * 16,
                       W + (size_t)(k0 + k) * M + col0 + u * 8);
        }
        cp_commit();
    };

    load_stage(0);
    load_stage(1);

    for (int kt = 0; kt < KT; kt++) {
        cp_wait1();
        __syncthreads();
        if (kt + 2 < KT) load_stage(kt + 2);
        else cp_commit();

        const uint32_t ab = sbase + (uint32_t)((kt % 3) * G_STAGE);
        const uint32_t bb = ab + GA_BYTES;

#pragma unroll
        for (int k16 = 0; k16 < 4; k16++) {
            uint32_t a[4][4];
#pragma unroll
            for (int mt = 0; mt < 4; mt++) {
                int m = warp_m * 64 + mt * 16 + (lane & 7) + ((lane >> 3) & 1) * 8;
                int u = k16 * 2 + (lane >> 4);
                LDSM_X4(a[mt][0], a[mt][1], a[mt][2], a[mt][3],
                        ab + m * 128 + ((u ^ (m & 7)) << 4));
            }
            uint32_t b[8][2];
#pragma unroll
            for (int ng = 0; ng < 4; ng++) {
                int k    = k16 * 16 + (lane & 7) + ((lane >> 3) & 1) * 8;
                int noff = warp_n * 64 + ng * 16 + ((lane >> 4) & 1) * 8;
                LDSM_X4T(b[ng*2][0], b[ng*2][1], b[ng*2+1][0], b[ng*2+1][1],
                         bb + k * GB_PITCH + noff * 2);
            }
#pragma unroll
            for (int mt = 0; mt < 4; mt++)
#pragma unroll
                for (int nt = 0; nt < 8; nt++)
                    mma_f16(acc[mt][nt], a[mt], b[nt][0], b[nt][1]);
        }
    }

#pragma unroll
    for (int nt = 0; nt < 8; nt++) {
        int ncol = col0 + warp_n * 64 + nt * 8 + (lane & 3) * 2;
        float bj0 = bias[ncol];
        float bj1 = bias[ncol + 1];
#pragma unroll
        for (int mt = 0; mt < 4; mt++) {
            int r0 = row0 + warp_m * 64 + mt * 16 + (lane >> 2);
            float v0 = (acc[mt][nt][0] + bj0) * oscale;
            float v1 = (acc[mt][nt][1] + bj1) * oscale;
            float v2 = (acc[mt][nt][2] + bj0) * oscale;
            float v3 = (acc[mt][nt][3] + bj1) * oscale;
            if (RELU) {
                v0 = fmaxf(v0, 0.0f); v1 = fmaxf(v1, 0.0f);
                v2 = fmaxf(v2, 0.0f); v3 = fmaxf(v3, 0.0f);
            }
            if (OUTH) {
                __half* Ch = (__half*)Cout;
                __half2 h0 = __floats2half2_rn(v0, v1);
                __half2 h1 = __floats2half2_rn(v2, v3);
                *(__half2*)(Ch + (size_t)r0 * M + ncol)       = h0;
                *(__half2*)(Ch + (size_t)(r0 + 8) * M + ncol) = h1;
            } else {
                float* Cf = (float*)Cout;
                *(float2*)(Cf + (size_t)r0 * M + ncol)       = make_float2(v0, v1);
                *(float2*)(Cf + (size_t)(r0 + 8) * M + ncol) = make_float2(v2, v3);
            }
        }
    }
}

template <bool RELU, bool OUTH>
__global__ void __launch_bounds__(G_THREADS) gemm_h_kernel(
    const __half* __restrict__ A, const __half* __restrict__ W,
    const float* __restrict__ bias, void* __restrict__ Cout, int K, int M)
{
    gemm_h_body<RELU, OUTH>(A, W, bias, Cout, K, M,
                            blockIdx.y * 128, blockIdx.x * 128, 1.0f);
}

#define QSCALE (0.125f * 1.4426950408889634f)   // 1/sqrt(64) * log2(e)

__global__ void __launch_bounds__(G_THREADS) qkv_h_kernel(
    const __half* __restrict__ x,
    const __half* __restrict__ wq, const float* __restrict__ bq,
    const __half* __restrict__ wk, const float* __restrict__ bk,
    const __half* __restrict__ wv, const float* __restrict__ bv,
    __half* __restrict__ q, __half* __restrict__ k, __half* __restrict__ v,
    int K, int M)
{
    const int z = blockIdx.z;
    const __half* W    = (z == 0) ? wq : (z == 1) ? wk : wv;
    const float*  bias = (z == 0) ? bq : (z == 1) ? bk : bv;
    __half*       C    = (z == 0) ? q  : (z == 1) ? k  : v;
    float oscale = (z == 0) ? QSCALE : 1.0f;
    gemm_h_body<false, true>(x, W, bias, C, K, M,
                             blockIdx.y * 128, blockIdx.x * 128, oscale);
}

// ===========================================================================
// Flash attention, fp16 mma, KV tile = 128: ONE softmax/rescale/barrier
// round per 128 KV rows (half the per-element softmax overhead of R7).
// CTA = (b,h) x 128 q rows; 8 warps x 16 q rows. 2-stage double buffer.
// K/V smem: [j][d] rows padded to 144B. P smem: [q][128] 256B rows, swizzled.
// ===========================================================================
#define AK_PITCH 144
#define AK_BYTES (128 * AK_PITCH)        // 18432 per stage
#define AV_OFF   (2 * AK_BYTES)          // V stages after K stages
#define AP_OFF   (4 * AK_BYTES)          // 73728
#define ATT_SMEM (AP_OFF + 128 * 256)    // + P 32768 = 106496

__global__ void __launch_bounds__(256, 1) attention_h_kernel(
    const __half* __restrict__ Q, const __half* __restrict__ K,
    const __half* __restrict__ V, __half* __restrict__ O)
{
    extern __shared__ char smem[];
    const uint32_t sbase = (uint32_t)__cvta_generic_to_shared(smem);

    const int tid  = threadIdx.x;
    const int lane = tid & 31;
    const int wid  = tid >> 5;
    const int b    = blockIdx.y >> 4;
    const int h    = blockIdx.y & 15;
    const int qr   = blockIdx.x * 128 + wid * 16;

    const __half* Qb = Q + ((size_t)(b * SEQ + qr)) * D_MODEL + h * HDIM;
    const __half* Kb = K + ((size_t)(b * SEQ)) * D_MODEL + h * HDIM;
    const __half* Vb = V + ((size_t)(b * SEQ)) * D_MODEL + h * HDIM;

    // Q fragments resident (q pre-scaled by QSCALE at the QKV epilogue)
    uint32_t qf[4][4];
    {
        const int r = lane >> 2, c2 = (lane & 3) * 2;
#pragma unroll
        for (int k16 = 0; k16 < 4; k16++) {
            qf[k16][0] = *(const uint32_t*)(Qb + (size_t)r * D_MODEL + k16 * 16 + c2);
            qf[k16][1] = *(const uint32_t*)(Qb + (size_t)(r + 8) * D_MODEL + k16 * 16 + c2);
            qf[k16][2] = *(const uint32_t*)(Qb + (size_t)r * D_MODEL + k16 * 16 + c2 + 8);
            qf[k16][3] = *(const uint32_t*)(Qb + (size_t)(r + 8) * D_MODEL + k16 * 16 + c2 + 8);
        }
    }

    // load one 128-row KV tile into stage st
    auto load_kv = [&](int kt, int st) {
        const __half* Kt = Kb + (size_t)kt * 128 * D_MODEL;
        const __half* Vt = Vb + (size_t)kt * 128 * D_MODEL;
        char* kd = smem + st * AK_BYTES;
        char* vd = smem + AV_OFF + st * AK_BYTES;
#pragma unroll
        for (int i = 0; i < 4; i++) {
            int c = tid + 256 * i;          // 0..1023
            int r = c >> 3, u = c & 7;      // 128 rows x 8 units
            cp_async16(kd + r * AK_PITCH + u * 16, Kt + (size_t)r * D_MODEL + u * 8);
            cp_async16(vd + r * AK_PITCH + u * 16, Vt + (size_t)r * D_MODEL + u * 8);
        }
        cp_commit();
    };

    float m0 = -1e30f, m1 = -1e30f, l0 = 0.0f, l1 = 0.0f;
    float oacc[8][4];
#pragma unroll
    for (int dt = 0; dt < 8; dt++)
#pragma unroll
        for (int r = 0; r < 4; r++) oacc[dt][r] = 0.0f;

    load_kv(0, 0);
    load_kv(1, 1);
    cp_wait1();
    __syncthreads();

    const int NKT = SEQ / 128;   // 16
    for (int kt = 0; kt < NKT; kt++) {
        const __half* kd = (const __half*)(smem + (kt & 1) * AK_BYTES);
        const uint32_t vdb = sbase + (uint32_t)(AV_OFF + (kt & 1) * AK_BYTES);

        // ---- S = Q @ K^T over 128 KV rows (16 n-tiles) ----
        float sacc[16][4];
#pragma unroll
        for (int nt = 0; nt < 16; nt++) {
            sacc[nt][0] = 0.0f; sacc[nt][1] = 0.0f;
            sacc[nt][2] = 0.0f; sacc[nt][3] = 0.0f;
            const int j = nt * 8 + (lane >> 2);
#pragma unroll
            for (int k16 = 0; k16 < 4; k16++) {
                int idx = j * 72 + k16 * 16 + (lane & 3) * 2;
                uint32_t b0 = *(const uint32_t*)(kd + idx);
                uint32_t b1 = *(const uint32_t*)(kd + idx + 8);
                mma_f16(sacc[nt], qf[k16], b0, b1);
            }
        }

        // ---- ONE softmax round per 128 rows (base 2) ----
        float mx0 = -1e30f, mx1 = -1e30f;
#pragma unroll
        for (int nt = 0; nt < 16; nt++) {
            mx0 = fmaxf(mx0, fmaxf(sacc[nt][0], sacc[nt][1]));
            mx1 = fmaxf(mx1, fmaxf(sacc[nt][2], sacc[nt][3]));
        }
        mx0 = fmaxf(mx0, __shfl_xor_sync(0xffffffffu, mx0, 1));
        mx0 = fmaxf(mx0, __shfl_xor_sync(0xffffffffu, mx0, 2));
        mx1 = fmaxf(mx1, __shfl_xor_sync(0xffffffffu, mx1, 1));
        mx1 = fmaxf(mx1, __shfl_xor_sync(0xffffffffu, mx1, 2));
        float mn0 = fmaxf(m0, mx0), mn1 = fmaxf(m1, mx1);
        float sc0 = exp2p(m0 - mn0), sc1 = exp2p(m1 - mn1);
        m0 = mn0; m1 = mn1;

        const int prow = wid * 16 + (lane >> 2);
        char* Pb = smem + AP_OFF;
        float rs0 = 0.0f, rs1 = 0.0f;
#pragma unroll
        for (int nt = 0; nt < 16; nt++) {
            float p0 = exp2p(sacc[nt][0] - mn0);
            float p1 = exp2p(sacc[nt][1] - mn0);
            float p2 = exp2p(sacc[nt][2] - mn1);
            float p3 = exp2p(sacc[nt][3] - mn1);
            rs0 += p0 + p1;
            rs1 += p2 + p3;
            __half2 hp0 = __floats2half2_rn(p0, p1);
            __half2 hp1 = __floats2half2_rn(p2, p3);
            // P row pitch 256B = 16 units; col nt lives in unit nt
            int bo = ((nt ^ (prow & 7)) << 4) + (lane & 3) * 4;
            *(__half2*)(Pb + prow * 256 + bo)       = hp0;
            *(__half2*)(Pb + (prow + 8) * 256 + bo) = hp1;
        }
        rs0 += __shfl_xor_sync(0xffffffffu, rs0, 1);
        rs0 += __shfl_xor_sync(0xffffffffu, rs0, 2);
        rs1 += __shfl_xor_sync(0xffffffffu, rs1, 1);
        rs1 += __shfl_xor_sync(0xffffffffu, rs1, 2);
        l0 = l0 * sc0 + rs0;
        l1 = l1 * sc1 + rs1;
#pragma unroll
        for (int dt = 0; dt < 8; dt++) {
            oacc[dt][0] *= sc0; oacc[dt][1] *= sc0;
            oacc[dt][2] *= sc1; oacc[dt][3] *= sc1;
        }
        __syncwarp();   // P rows are warp-private: warp sync suffices

        // ---- O += P @ V  (128 j rows = 8 k16 blocks) ----
        const uint32_t pbb = sbase + AP_OFF;
#pragma unroll
        for (int k16 = 0; k16 < 8; k16++) {
            uint32_t pf[4];
            {
                int row = wid * 16 + (lane & 7) + ((lane >> 3) & 1) * 8;
                int u   = k16 * 2 + (lane >> 4);
                LDSM_X4(pf[0], pf[1], pf[2], pf[3],
                        pbb + row * 256 + ((u ^ (row & 7)) << 4));
            }
            uint32_t vb[8][2];
#pragma unroll
            for (int ng = 0; ng < 4; ng++) {
                int j    = k16 * 16 + (lane & 7) + ((lane >> 3) & 1) * 8;
                int doff = ng * 16 + ((lane >> 4) & 1) * 8;
                LDSM_X4T(vb[ng*2][0], vb[ng*2][1], vb[ng*2+1][0], vb[ng*2+1][1],
                         vdb + j * AK_PITCH + doff * 2);
            }
#pragma unroll
            for (int dt = 0; dt < 8; dt++)
                mma_f16(oacc[dt], pf, vb[dt][0], vb[dt][1]);
        }

        __syncthreads();                       // done reading stage kt&1
        if (kt + 2 < NKT) load_kv(kt + 2, kt & 1);
        else cp_commit();
        cp_wait1();                            // (kt+1)'s tile landed
        __syncthreads();
    }

    // ---- normalize + write ctx (half) ----
    float inv0 = 1.0f / l0, inv1 = 1.0f / l1;
    const size_t row0 = (size_t)(b * SEQ + qr + (lane >> 2));
#pragma unroll
    for (int dt = 0; dt < 8; dt++) {
        int col = h * HDIM + dt * 8 + 2 * (lane & 3);
        __half2 h0 = __floats2half2_rn(oacc[dt][0] * inv0, oacc[dt][1] * inv0);
        __half2 h1 = __floats2half2_rn(oacc[dt][2] * inv1, oacc[dt][3] * inv1);
        *(__half2*)(O + row0 * D_MODEL + col)       = h0;
        *(__half2*)(O + (row0 + 8) * D_MODEL + col) = h1;
    }
}

// ---------------------------------------------------------------------------
// Fused residual add + LayerNorm; optional half output copy
// ---------------------------------------------------------------------------
__global__ void __launch_bounds__(256) add_ln_kernel(
    const float* __restrict__ A, const float* __restrict__ R,
    const float* __restrict__ g, const float* __restrict__ beta,
    float* __restrict__ out, __half* __restrict__ out_h)
{
    const int row = blockIdx.x;
    const int t   = threadIdx.x;

    float4 a = *(const float4*)(A + (size_t)row * D_MODEL + t * 4);
    float4 r = *(const float4*)(R + (size_t)row * D_MODEL + t * 4);
    float x0 = a.x + r.x, x1 = a.y + r.y, x2 = a.z + r.z, x3 = a.w + r.w;

    float sum = x0 + x1 + x2 + x3;
    float sq  = x0 * x0 + x1 * x1 + x2 * x2 + x3 * x3;

#pragma unroll
    for (int w = 16; w >= 1; w >>= 1) {
        sum += __shfl_xor_sync(0xffffffffu, sum, w);
        sq  += __shfl_xor_sync(0xffffffffu, sq, w);
    }
    __shared__ float ssum[8], ssq[8];
    __shared__ float s_mu, s_rstd;
    if ((t & 31) == 0) {
        ssum[t >> 5] = sum;
        ssq[t >> 5]  = sq;
    }
    __syncthreads();
    if (t == 0) {
        float S = 0.0f, Q = 0.0f;
#pragma unroll
        for (int i = 0; i < 8; i++) { S += ssum[i]; Q += ssq[i]; }
        float mu  = S * (1.0f / D_MODEL);
        float var = Q * (1.0f / D_MODEL) - mu * mu;
        s_mu   = mu;
        s_rstd = rsqrtf(var + 1e-5f);
    }
    __syncthreads();
    float mu = s_mu, rstd = s_rstd;

    float4 gg = *(const float4*)(g + t * 4);
    float4 bb = *(const float4*)(beta + t * 4);
    float4 ov;
    ov.x = (x0 - mu) * rstd * gg.x + bb.x;
    ov.y = (x1 - mu) * rstd * gg.y + bb.y;
    ov.z = (x2 - mu) * rstd * gg.z + bb.z;
    ov.w = (x3 - mu) * rstd * gg.w + bb.w;
    *(float4*)(out + (size_t)row * D_MODEL + t * 4) = ov;
    if (out_h) {
        __half2 h0 = __floats2half2_rn(ov.x, ov.y);
        __half2 h1 = __floats2half2_rn(ov.z, ov.w);
        uint2 pk;
        pk.x = *(uint32_t*)&h0;
        pk.y = *(uint32_t*)&h1;
        *(uint2*)(out_h + (size_t)row * D_MODEL + t * 4) = pk;
    }
}

// ---------------------------------------------------------------------------
extern "C" void kernel_launch(void* const* d_in, const int* in_sizes, int n_in,
                              void* d_out, int out_size)
{
    (void)in_sizes; (void)n_in; (void)out_size;

    const float* x     = (const float*)d_in[0];
    const float* w_q   = (const float*)d_in[1];
    const float* b_q   = (const float*)d_in[2];
    const float* w_k   = (const float*)d_in[3];
    const float* b_k   = (const float*)d_in[4];
    const float* w_v   = (const float*)d_in[5];
    const float* b_v   = (const float*)d_in[6];
    const float* w_o   = (const float*)d_in[7];
    const float* b_o   = (const float*)d_in[8];
    const float* w_ff1 = (const float*)d_in[9];
    const float* b_ff1 = (const float*)d_in[10];
    const float* w_ff2 = (const float*)d_in[11];
    const float* b_ff2 = (const float*)d_in[12];
    const float* ln1_g = (const float*)d_in[13];
    const float* ln1_b = (const float*)d_in[14];
    const float* ln2_g = (const float*)d_in[15];
    const float* ln2_b = (const float*)d_in[16];
    float* out = (float*)d_out;

    __half *qh, *kh, *vh, *ctxh, *hh, *ffh;
    __half *xh, *wqh, *wkh, *wvh, *woh, *ff1h, *ff2h;
    float *t1, *h;
    cudaGetSymbolAddress((void**)&qh,   g_qh);
    cudaGetSymbolAddress((void**)&kh,   g_kh);
    cudaGetSymbolAddress((void**)&vh,   g_vh);
    cudaGetSymbolAddress((void**)&ctxh, g_ctxh);
    cudaGetSymbolAddress((void**)&t1,   g_t1);
    cudaGetSymbolAddress((void**)&h,    g_h);
    cudaGetSymbolAddress((void**)&hh,   g_hh);
    cudaGetSymbolAddress((void**)&ffh,  g_ffh);
    cudaGetSymbolAddress((void**)&xh,   g_xh);
    cudaGetSymbolAddress((void**)&wqh,  g_wqh);
    cudaGetSymbolAddress((void**)&wkh,  g_wkh);
    cudaGetSymbolAddress((void**)&wvh,  g_wvh);
    cudaGetSymbolAddress((void**)&woh,  g_woh);
    cudaGetSymbolAddress((void**)&ff1h, g_ff1h);
    cudaGetSymbolAddress((void**)&ff2h, g_ff2h);

    cudaFuncSetAttribute(attention_h_kernel,
                         cudaFuncAttributeMaxDynamicSharedMemorySize, ATT_SMEM);
    cudaFuncSetAttribute(qkv_h_kernel,
                         cudaFuncAttributeMaxDynamicSharedMemorySize, G_SMEM);
    cudaFuncSetAttribute(gemm_h_kernel<false, false>,
                         cudaFuncAttributeMaxDynamicSharedMemorySize, G_SMEM);
    cudaFuncSetAttribute(gemm_h_kernel<true, true>,
                         cudaFuncAttributeMaxDynamicSharedMemorySize, G_SMEM);

    dim3 gblk(G_THREADS);

    // 1) fp32 -> fp16 prepass (single launch)
    conv_all_kernel<<<(R_TOTAL + 255) / 256, 256>>>(
        (const float4*)x, xh,
        (const float4*)w_q, wqh,
        (const float4*)w_k, wkh,
        (const float4*)w_v, wvh,
        (const float4*)w_o, woh,
        (const float4*)w_ff1, ff1h,
        (const float4*)w_ff2, ff2h);

    // 2) QKV projections (fused, grid.z = 3; q pre-scaled by QSCALE)
    qkv_h_kernel<<<dim3(D_MODEL / 128, NTOK / 128, 3), gblk, G_SMEM>>>(
        xh, wqh, b_q, wkh, b_k, wvh, b_v, qh, kh, vh, D_MODEL, D_MODEL);

    // 3) flash attention (KV tile 128) -> ctx (half)
    attention_h_kernel<<<dim3(SEQ / 128, BATCH * NHEAD), 256, ATT_SMEM>>>(
        qh, kh, vh, ctxh);

    // 4) output projection -> t1 (fp32)
    gemm_h_kernel<false, false><<<dim3(D_MODEL / 128, NTOK / 128), gblk, G_SMEM>>>(
        ctxh, woh, b_o, t1, D_MODEL, D_MODEL);

    // 5) AddNorm1 -> h (fp32) + hh (half)
    add_ln_kernel<<<NTOK, 256>>>(x, t1, ln1_g, ln1_b, h, hh);

    // 6) FFN1 (ReLU) -> ffh (half)
    gemm_h_kernel<true, true><<<dim3(D_FF / 128, NTOK / 128), gblk, G_SMEM>>>(
        hh, ff1h, b_ff1, ffh, D_MODEL, D_FF);

    // 7) FFN2 -> t1 (fp32)
    gemm_h_kernel<false, false><<<dim3(D_MODEL / 128, NTOK / 128), gblk, G_SMEM>>>(
        ffh, ff2h, b_ff2, t1, D_FF, D_MODEL);

    // 8) AddNorm2 -> output
    add_ln_kernel<<<NTOK, 256>>>(h, t1, ln2_g, ln2_b, out, nullptr);
}